// round 12
// baseline (speedup 1.0000x reference)
#include <cuda_runtime.h>
#include <cuda_fp16.h>
#include <stdint.h>

#define TINV 10.0f

__device__ float d_agn[128 * 128];
__device__ float d_ofinv[128 * 1024];
__device__ __half d_ofh[128ull * 1024 * 256];  // [bb][s][d] f16; bb: q 0-63, k 64-127
__device__ float d_xn[2][64 * 1024 * 128];     // normalized x, [b][s][c] f32
__device__ __half d_xh[2][64 * 1024 * 128];    // normalized x, f16 copy
__device__ unsigned long long d_rowbest[64 * 1024];
__device__ unsigned long long d_colbest[64 * 1024];
__device__ double d_gsum, d_dsum;

// ---------------- helpers ----------------
__device__ __forceinline__ uint32_t smem_u32(const void* p) {
    uint32_t a;
    asm("{ .reg .u64 t; cvta.to.shared.u64 t, %1; cvt.u32.u64 %0, t; }" : "=r"(a) : "l"(p));
    return a;
}
__device__ __forceinline__ uint32_t fkey(float f) {
    uint32_t u = __float_as_uint(f);
    return (u & 0x80000000u) ? ~u : (u | 0x80000000u);
}
__device__ __forceinline__ unsigned long long packkey(float v, uint32_t idx) {
    return ((unsigned long long)fkey(v) << 32) | (unsigned long long)(0xFFFFFFFFu - idx);
}
__device__ __forceinline__ unsigned long long shflx64(unsigned long long v, int m) {
    return __shfl_xor_sync(0xFFFFFFFFu, v, m);
}
__device__ __forceinline__ void cp16(uint32_t dst, const void* src) {
    asm volatile("cp.async.cg.shared.global [%0],[%1],16;\n" :: "r"(dst), "l"(src));
}
#define CP_COMMIT() asm volatile("cp.async.commit_group;\n" ::: "memory")
#define CP_WAIT(n)  asm volatile("cp.async.wait_group %0;\n" :: "n"(n) : "memory")
__device__ __forceinline__ void ldsm4(uint32_t& r0, uint32_t& r1, uint32_t& r2,
                                      uint32_t& r3, uint32_t a) {
    asm volatile("ldmatrix.sync.aligned.m8n8.x4.shared.b16 {%0,%1,%2,%3},[%4];\n"
                 : "=r"(r0), "=r"(r1), "=r"(r2), "=r"(r3) : "r"(a));
}
__device__ __forceinline__ void mma16816h(uint32_t* c, const uint32_t* a, const uint32_t* b) {
    asm volatile("mma.sync.aligned.m16n8k16.row.col.f16.f16.f16.f16 "
                 "{%0,%1},{%2,%3,%4,%5},{%6,%7},{%0,%1};\n"
                 : "+r"(c[0]), "+r"(c[1])
                 : "r"(a[0]), "r"(a[1]), "r"(a[2]), "r"(a[3]), "r"(b[0]), "r"(b[1]));
}
__device__ __forceinline__ void mma16816f(float* c, const uint32_t* a, const uint32_t* b) {
    asm volatile("mma.sync.aligned.m16n8k16.row.col.f32.f16.f16.f32 "
                 "{%0,%1,%2,%3},{%4,%5,%6,%7},{%8,%9},{%0,%1,%2,%3};\n"
                 : "+f"(c[0]), "+f"(c[1]), "+f"(c[2]), "+f"(c[3])
                 : "r"(a[0]), "r"(a[1]), "r"(a[2]), "r"(a[3]), "r"(b[0]), "r"(b[1]));
}

// ---------------- agn (+ scratch init folded in) ----------------
__global__ void k_agn(const float* __restrict__ agq, const float* __restrict__ agk) {
    int row = blockIdx.x, c = threadIdx.x;
    int gt = row * 128 + c;
#pragma unroll
    for (int i = 0; i < 4; i++) {
        d_rowbest[gt * 4 + i] = 0ULL;
        d_colbest[gt * 4 + i] = 0ULL;
    }
    if (gt == 0) { d_gsum = 0.0; d_dsum = 0.0; }

    const float* src = (row < 64) ? (agq + row * 128) : (agk + (row - 64) * 128);
    float v = src[c];
    __shared__ float red[128];
    red[c] = v * v; __syncthreads();
    for (int off = 64; off; off >>= 1) { if (c < off) red[c] += red[c + off]; __syncthreads(); }
    d_agn[row * 128 + c] = v / fmaxf(sqrtf(red[0]), 1e-12f);
}
__global__ void k_global() {
    int i = blockIdx.x, j = threadIdx.x;
    __shared__ float ai[128], red[128], s_pos;
    ai[j] = d_agn[i * 128 + j];
    __syncthreads();
    float dot = 0.0f;
#pragma unroll 8
    for (int c = 0; c < 128; c++) dot += ai[c] * d_agn[j * 128 + c];
    float lg = dot * TINV;
    if (j == ((i + 64) & 127)) s_pos = lg;
    float v = (j == i) ? -1e30f : lg;
    red[j] = v; __syncthreads();
    for (int off = 64; off; off >>= 1) { if (j < off) red[j] = fmaxf(red[j], red[j + off]); __syncthreads(); }
    float mx = red[0]; __syncthreads();
    red[j] = expf(v - mx); __syncthreads();
    for (int off = 64; off; off >>= 1) { if (j < off) red[j] += red[j + off]; __syncthreads(); }
    if (j == 0) atomicAdd(&d_gsum, (double)(logf(red[0]) + mx - s_pos));
}

// ---------------- of: transpose -> [s][d] f16 + col inv-norms ----------------
__global__ void __launch_bounds__(256) k_prep_of(const float* __restrict__ ofq,
                                                 const float* __restrict__ ofk) {
    __shared__ float sh[32 * 257];
    int bb = blockIdx.y, s0 = blockIdx.x * 32, tid = threadIdx.x;
    const float* p = (bb < 64 ? ofq : ofk) + (size_t)(bb & 63) * 256 * 1024;
#pragma unroll
    for (int it = 0; it < 8; it++) {
        int idx = it * 256 + tid;
        int dd = idx >> 3, s4 = idx & 7;
        float4 v = *(const float4*)&p[(size_t)dd * 1024 + s0 + s4 * 4];
        sh[(s4 * 4 + 0) * 257 + dd] = v.x;
        sh[(s4 * 4 + 1) * 257 + dd] = v.y;
        sh[(s4 * 4 + 2) * 257 + dd] = v.z;
        sh[(s4 * 4 + 3) * 257 + dd] = v.w;
    }
    __syncthreads();
    int s = tid >> 3, part = tid & 7, d0 = part * 32;
    const float* row = &sh[s * 257 + d0];
    float acc = 0.0f;
    uint32_t pk[16];
#pragma unroll
    for (int ii = 0; ii < 16; ii++) {
        int i = (ii + part * 2) & 15;
        float a = row[2 * i], b2 = row[2 * i + 1];
        acc += a * a + b2 * b2;
        __half2 h = __floats2half2_rn(a, b2);
        pk[i] = *reinterpret_cast<uint32_t*>(&h);
    }
    acc += __shfl_xor_sync(0xFFFFFFFFu, acc, 1);
    acc += __shfl_xor_sync(0xFFFFFFFFu, acc, 2);
    acc += __shfl_xor_sync(0xFFFFFFFFu, acc, 4);
    if (part == 0) d_ofinv[bb * 1024 + s0 + s] = 1.0f / fmaxf(sqrtf(acc), 1e-12f);
    uint4* dst = (uint4*)(d_ofh + ((size_t)bb * 1024 + s0 + s) * 256 + d0);
#pragma unroll
    for (int q = 0; q < 4; q++)
        dst[q] = make_uint4(pk[q * 4], pk[q * 4 + 1], pk[q * 4 + 2], pk[q * 4 + 3]);
}

// ---------------- x: normalize over C + transpose (f32 + f16 outputs) ----------
__global__ void __launch_bounds__(256) k_prep_x(const float* __restrict__ xq,
                                                const float* __restrict__ xk) {
    __shared__ float sh[128 * 33];
    __shared__ float invs[32];
    int bb = blockIdx.y, s0 = blockIdx.x * 32, tid = threadIdx.x;
    const float* src = (bb < 64 ? xq : xk) + (size_t)(bb & 63) * 128 * 1024;
    int side = bb < 64 ? 0 : 1;
    float* dst = d_xn[side] + (size_t)(bb & 63) * 1024 * 128;
    __half* dsth = d_xh[side] + (size_t)(bb & 63) * 1024 * 128;
#pragma unroll
    for (int it = 0; it < 4; it++) {
        int idx = it * 256 + tid;
        int c = idx >> 3, s4 = idx & 7;
        float4 v = *(const float4*)&src[(size_t)c * 1024 + s0 + s4 * 4];
        sh[c * 33 + s4 * 4 + 0] = v.x;
        sh[c * 33 + s4 * 4 + 1] = v.y;
        sh[c * 33 + s4 * 4 + 2] = v.z;
        sh[c * 33 + s4 * 4 + 3] = v.w;
    }
    __syncthreads();
    if (tid < 32) {
        float acc = 0.0f;
#pragma unroll 8
        for (int c = 0; c < 128; c++) { float v = sh[c * 33 + tid]; acc += v * v; }
        invs[tid] = 1.0f / fmaxf(sqrtf(acc), 1e-12f);
    }
    __syncthreads();
#pragma unroll
    for (int it = 0; it < 8; it++) {
        int idx = it * 256 + tid, s = idx >> 6, c2 = (idx & 63) * 2;
        float inv = invs[s];
        float a = sh[c2 * 33 + s] * inv, b2 = sh[(c2 + 1) * 33 + s] * inv;
        float2* d2 = (float2*)&dst[(size_t)(s0 + s) * 128 + c2];
        *d2 = make_float2(a, b2);
        __half2 h = __floats2half2_rn(a, b2);
        *(uint32_t*)&dsth[(size_t)(s0 + s) * 128 + c2] = *reinterpret_cast<uint32_t*>(&h);
    }
}

// ---------------- sim GEMM: B-resident (256t x K256), loop 8 s-tiles ----------
// grid (4 t-tiles, 64 b) = 256 CTAs, 1 CTA/SM, 192KB dyn smem.
// smem: A0 32KB | A1 32KB | B 128KB. A chunk = 128 s x 128 K (f16, 256B rows).
#define SIM_SMEM 196608
__global__ void __launch_bounds__(256, 1) k_simargmax() {
    extern __shared__ __align__(16) char dsm[];
    __shared__ float qf[128], kf[256];
    __shared__ unsigned long long s_row[128], s_col[256];
    int tid = threadIdx.x, lane = tid & 31, wid = tid >> 5;
    int b = blockIdx.y, t0 = blockIdx.x * 256;
    const char* Aq = (const char*)(d_ofh + (size_t)b * 1024 * 256);
    const char* Bq = (const char*)(d_ofh + ((size_t)(64 + b) * 1024 + t0) * 256);

    kf[tid] = d_ofinv[(64 + b) * 1024 + t0 + tid];
    s_col[tid] = 0ULL;
    if (tid < 128) { qf[tid] = d_ofinv[b * 1024 + tid]; s_row[tid] = 0ULL; }

    uint32_t base = smem_u32(dsm);
    uint32_t a0 = base, a1 = base + 32768, bbuf = base + 65536;

    // B K-half loader (4096 ops each), rows 512B, 32 16B-units swizzled
#define LOAD_BH(kc) do { \
    _Pragma("unroll") \
    for (int it = 0; it < 16; it++) { \
        int idx = it * 256 + tid, r = idx >> 4, u = (kc) * 16 + (idx & 15); \
        cp16(bbuf + (uint32_t)r * 512 + (uint32_t)(((u & 24) | ((u & 7) ^ (r & 7))) << 4), \
             Bq + (size_t)r * 512 + u * 16); \
    } \
    CP_COMMIT(); } while (0)
    // A chunk loader: tile t, K-half kc -> buffer ab (128 rows x 256B)
#define LOAD_A(t, kc, ab) do { \
    _Pragma("unroll") \
    for (int it = 0; it < 8; it++) { \
        int idx = it * 256 + tid, r = idx >> 4, u = idx & 15; \
        cp16((ab) + (uint32_t)r * 256 + (uint32_t)(((u & 8) | ((u & 7) ^ (r & 7))) << 4), \
             Aq + (size_t)((t) * 128 + r) * 512 + (kc) * 256 + u * 16); \
    } \
    CP_COMMIT(); } while (0)

    LOAD_BH(0);        // g0
    LOAD_A(0, 0, a0);  // g1
    LOAD_BH(1);        // g2
    LOAD_A(0, 1, a1);  // g3

    int wm = wid & 1, wn = wid >> 1;      // warp tile: rows wm*64, cols wn*64
    int row_in = lane & 15, ub = lane >> 4;
    int g = lane >> 2, tg = lane & 3;
    uint32_t acc[4][8][2];
#pragma unroll
    for (int mi = 0; mi < 4; mi++)
#pragma unroll
        for (int ni = 0; ni < 8; ni++) { acc[mi][ni][0] = 0u; acc[mi][ni][1] = 0u; }

#define COMPUTE(ab, kc) do { \
    _Pragma("unroll") \
    for (int ks = 0; ks < 8; ks++) { \
        int u = ks * 2 + ub; \
        int ug = (kc) * 16 + ks * 2 + ub; \
        uint32_t af[4][4], bfr[8][2]; \
        _Pragma("unroll") \
        for (int mi = 0; mi < 4; mi++) { \
            int r = wm * 64 + mi * 16 + row_in; \
            ldsm4(af[mi][0], af[mi][1], af[mi][2], af[mi][3], \
                  (ab) + (uint32_t)r * 256 + (uint32_t)(((u & 8) | ((u & 7) ^ (r & 7))) << 4)); \
        } \
        _Pragma("unroll") \
        for (int np = 0; np < 4; np++) { \
            int r = wn * 64 + np * 16 + row_in; \
            uint32_t r0, r1, r2, r3; \
            ldsm4(r0, r1, r2, r3, \
                  bbuf + (uint32_t)r * 512 + (uint32_t)(((ug & 24) | ((ug & 7) ^ (r & 7))) << 4)); \
            bfr[np * 2][0] = r0; bfr[np * 2][1] = r2; \
            bfr[np * 2 + 1][0] = r1; bfr[np * 2 + 1][1] = r3; \
        } \
        _Pragma("unroll") \
        for (int mi = 0; mi < 4; mi++) \
            _Pragma("unroll") \
            for (int ni = 0; ni < 8; ni++) \
                mma16816h(acc[mi][ni], af[mi], bfr[ni]); \
    } } while (0)

    for (int t = 0; t < 8; t++) {
        // chunk kc=0 (buffer a0)
        if (t == 0) CP_WAIT(2); else CP_WAIT(1);
        __syncthreads();
        COMPUTE(a0, 0);
        if (t < 7) { __syncthreads(); LOAD_A(t + 1, 0, a0); }
        // chunk kc=1 (buffer a1)
        if (t == 7) CP_WAIT(0); else CP_WAIT(1);
        __syncthreads();
        COMPUTE(a1, 1);
        if (t < 7) { __syncthreads(); LOAD_A(t + 1, 1, a1); }

        // ---- epilogue for this s-tile ----
        int s0 = t * 128;
        // row argmax (over t-cols): weight kf
#pragma unroll
        for (int mi = 0; mi < 4; mi++)
#pragma unroll
            for (int rh = 0; rh < 2; rh++) {
                unsigned long long best = 0ULL;
#pragma unroll
                for (int ni = 0; ni < 8; ni++) {
                    float2 v = __half22float2(*reinterpret_cast<__half2*>(&acc[mi][ni][rh]));
                    int tl0 = wn * 64 + ni * 8 + 2 * tg;
                    unsigned long long k0 = packkey(v.x * kf[tl0], (uint32_t)(t0 + tl0));
                    unsigned long long k1 = packkey(v.y * kf[tl0 + 1], (uint32_t)(t0 + tl0 + 1));
                    if (k0 > best) best = k0;
                    if (k1 > best) best = k1;
                }
                unsigned long long o;
                o = shflx64(best, 1); best = (o > best) ? o : best;
                o = shflx64(best, 2); best = (o > best) ? o : best;
                if (tg == 0)
                    atomicMax(&s_row[wm * 64 + mi * 16 + g + 8 * rh], best);
            }
        // col argmax (over s-rows): weight qf (this tile's)
#pragma unroll
        for (int ni = 0; ni < 8; ni++)
#pragma unroll
            for (int cp = 0; cp < 2; cp++) {
                int tl = wn * 64 + ni * 8 + 2 * tg + cp;
                unsigned long long best = 0ULL;
#pragma unroll
                for (int mi = 0; mi < 4; mi++)
#pragma unroll
                    for (int rh = 0; rh < 2; rh++) {
                        __half2 h = *reinterpret_cast<__half2*>(&acc[mi][ni][rh]);
                        float vv = cp ? __high2float(h) : __low2float(h);
                        int sl = wm * 64 + mi * 16 + g + 8 * rh;
                        unsigned long long k2 = packkey(vv * qf[sl], (uint32_t)(s0 + sl));
                        if (k2 > best) best = k2;
                    }
                unsigned long long o;
                o = shflx64(best, 4);  best = (o > best) ? o : best;
                o = shflx64(best, 8);  best = (o > best) ? o : best;
                o = shflx64(best, 16); best = (o > best) ? o : best;
                if (g == 0) atomicMax(&s_col[tl], best);
            }
        __syncthreads();
        if (tid < 128) {
            atomicMax(&d_rowbest[(size_t)b * 1024 + s0 + tid], s_row[tid]);
            s_row[tid] = 0ULL;
            if (t < 7) qf[tid] = d_ofinv[b * 1024 + (t + 1) * 128 + tid];
        }
        // reset accumulators
#pragma unroll
        for (int mi = 0; mi < 4; mi++)
#pragma unroll
            for (int ni = 0; ni < 8; ni++) { acc[mi][ni][0] = 0u; acc[mi][ni][1] = 0u; }
    }
#undef COMPUTE
#undef LOAD_A
#undef LOAD_BH

    // col results: this CTA covered ALL s for its 256 t-columns -> plain store
    d_colbest[(size_t)b * 1024 + t0 + tid] = s_col[tid];
}

// ---------------- dense losses: tensor-core neg GEMM + CE ----------------
#define DEN_SMEM 49152
__global__ void __launch_bounds__(256, 2) k_dense(const float* __restrict__ adq,
                                                  const float* __restrict__ adk) {
    extern __shared__ __align__(16) char dsm[];
    __shared__ float posv[128];
    int b = blockIdx.y, dir = blockIdx.z, s0 = blockIdx.x * 128;
    const __half* xhA = d_xh[dir] + (size_t)b * 1024 * 128;
    const float* xA = d_xn[dir] + (size_t)b * 1024 * 128;
    const float* xB = d_xn[dir ^ 1] + (size_t)b * 1024 * 128;
    const float* ad = dir ? adq : adk;
    const unsigned long long* best = dir ? d_colbest : d_rowbest;

    int tid = threadIdx.x, lane = tid & 31, wid = tid >> 5;
    uint32_t a_base = smem_u32(dsm), b_base = a_base + 32768;
    float* Ls = (float*)dsm;

#pragma unroll
    for (int it = 0; it < 8; it++) {
        int idx = it * 256 + tid, row = idx >> 4, u = idx & 15;
        cp16(a_base + (uint32_t)row * 256 + (uint32_t)(((u & 8) | ((u & 7) ^ (row & 7))) << 4),
             (const char*)xhA + (size_t)(s0 + row) * 256 + u * 16);
    }
    CP_COMMIT();
#pragma unroll
    for (int it = 0; it < 4; it++) {
        int idx = it * 256 + tid, j = idx >> 4, u = idx & 15;
        float4 v0 = *(const float4*)&ad[j * 128 + u * 8];
        float4 v1 = *(const float4*)&ad[j * 128 + u * 8 + 4];
        __half2 h0 = __floats2half2_rn(v0.x, v0.y), h1 = __floats2half2_rn(v0.z, v0.w);
        __half2 h2 = __floats2half2_rn(v1.x, v1.y), h3 = __floats2half2_rn(v1.z, v1.w);
        uint4 pk = make_uint4(*(uint32_t*)&h0, *(uint32_t*)&h1, *(uint32_t*)&h2, *(uint32_t*)&h3);
        *(uint4*)(dsm + 32768 + j * 256 + (((u & 8) | ((u & 7) ^ (j & 7))) << 4)) = pk;
    }
    for (int rr = 0; rr < 16; rr++) {
        int r = wid * 16 + rr, sgl = s0 + r;
        unsigned long long bk = best[b * 1024 + sgl];
        int ind = (int)(0xFFFFFFFFu - (uint32_t)(bk & 0xFFFFFFFFull));
        float sum = 0.0f;
#pragma unroll
        for (int c = lane; c < 128; c += 32)
            sum += xA[(size_t)sgl * 128 + c] * xB[(size_t)ind * 128 + c];
#pragma unroll
        for (int off = 16; off; off >>= 1) sum += __shfl_xor_sync(0xFFFFFFFFu, sum, off);
        if (lane == 0) posv[r] = sum * TINV;
    }
    asm volatile("cp.async.wait_group 0;\n" ::: "memory");
    __syncthreads();

    int wm = wid & 3, wn = wid >> 2;
    int row_in = lane & 15, ub = lane >> 4;
    float acc[2][4][4];
#pragma unroll
    for (int mi = 0; mi < 2; mi++)
#pragma unroll
        for (int ni = 0; ni < 4; ni++)
#pragma unroll
            for (int r = 0; r < 4; r++) acc[mi][ni][r] = 0.0f;
#pragma unroll
    for (int ks = 0; ks < 8; ks++) {
        int u = ks * 2 + ub;
        uint32_t af[2][4], bfr[4][2];
#pragma unroll
        for (int mi = 0; mi < 2; mi++) {
            int r = wm * 32 + mi * 16 + row_in;
            ldsm4(af[mi][0], af[mi][1], af[mi][2], af[mi][3],
                  a_base + (uint32_t)r * 256 + (uint32_t)(((u & 8) | ((u & 7) ^ (r & 7))) << 4));
        }
#pragma unroll
        for (int np = 0; np < 2; np++) {
            int r = wn * 32 + np * 16 + row_in;
            uint32_t r0, r1, r2, r3;
            ldsm4(r0, r1, r2, r3,
                  b_base + (uint32_t)r * 256 + (uint32_t)(((u & 8) | ((u & 7) ^ (r & 7))) << 4));
            bfr[np * 2][0] = r0; bfr[np * 2][1] = r2;
            bfr[np * 2 + 1][0] = r1; bfr[np * 2 + 1][1] = r3;
        }
#pragma unroll
        for (int mi = 0; mi < 2; mi++)
#pragma unroll
            for (int ni = 0; ni < 4; ni++)
                mma16816f(acc[mi][ni], af[mi], bfr[ni]);
    }
    __syncthreads();

    int g = lane >> 2, tg = lane & 3;
#pragma unroll
    for (int mi = 0; mi < 2; mi++)
#pragma unroll
        for (int ni = 0; ni < 4; ni++)
#pragma unroll
            for (int rh = 0; rh < 2; rh++)
#pragma unroll
                for (int cp = 0; cp < 2; cp++) {
                    int r = wm * 32 + mi * 16 + g + 8 * rh;
                    int c = wn * 32 + ni * 8 + 2 * tg + cp;
                    Ls[r * 65 + c] = acc[mi][ni][rh * 2 + cp] * TINV;
                }
    __syncthreads();

    float wsum = 0.0f;
    for (int rr = 0; rr < 16; rr++) {
        int r = wid * 16 + rr;
        float v0 = Ls[r * 65 + lane], v1 = Ls[r * 65 + lane + 32];
        if (lane == b) v0 = -1e30f;
        if (lane + 32 == b) v1 = -1e30f;
        float pos = posv[r];
        float mx = fmaxf(fmaxf(v0, v1), pos);
#pragma unroll
        for (int off = 16; off; off >>= 1) mx = fmaxf(mx, __shfl_xor_sync(0xFFFFFFFFu, mx, off));
        float e = expf(v0 - mx) + expf(v1 - mx);
#pragma unroll
        for (int off = 16; off; off >>= 1) e += __shfl_xor_sync(0xFFFFFFFFu, e, off);
        if (lane == 0) wsum += logf(e + expf(pos - mx)) + mx - pos;
    }
    if (lane == 0) atomicAdd(&d_dsum, (double)wsum);
}

__global__ void k_final(const int* __restrict__ epoch, float* __restrict__ out) {
    float g = (float)(d_gsum / 128.0);
    float d = (float)(d_dsum / 131072.0);
    out[0] = (*epoch > 0) ? (0.5f * g + 0.5f * d) : g;
}

extern "C" void kernel_launch(void* const* d_in, const int* in_sizes, int n_in,
                              void* d_out, int out_size) {
    const float* ofq = (const float*)d_in[0];
    const float* agq = (const float*)d_in[1];
    const float* xq  = (const float*)d_in[2];
    const float* adq = (const float*)d_in[3];
    const float* ofk = (const float*)d_in[4];
    const float* agk = (const float*)d_in[5];
    const float* xk  = (const float*)d_in[6];
    const float* adk = (const float*)d_in[7];
    const int* epoch = (const int*)d_in[8];
    float* out = (float*)d_out;

    static bool init_done = false;
    static cudaStream_t s1, s2;
    static cudaEvent_t eFork, eAgn, eGlob, ePx;
    if (!init_done) {
        cudaFuncSetAttribute(k_simargmax, cudaFuncAttributeMaxDynamicSharedMemorySize, SIM_SMEM);
        cudaFuncSetAttribute(k_dense, cudaFuncAttributeMaxDynamicSharedMemorySize, DEN_SMEM);
        cudaStreamCreateWithFlags(&s1, cudaStreamNonBlocking);
        cudaStreamCreateWithFlags(&s2, cudaStreamNonBlocking);
        cudaEventCreateWithFlags(&eFork, cudaEventDisableTiming);
        cudaEventCreateWithFlags(&eAgn, cudaEventDisableTiming);
        cudaEventCreateWithFlags(&eGlob, cudaEventDisableTiming);
        cudaEventCreateWithFlags(&ePx, cudaEventDisableTiming);
        init_done = true;
    }

    cudaEventRecord(eFork, 0);
    cudaStreamWaitEvent(s1, eFork, 0);
    cudaStreamWaitEvent(s2, eFork, 0);

    // s1: agn (zeroes scratch) -> global
    k_agn<<<128, 128, 0, s1>>>(agq, agk);
    cudaEventRecord(eAgn, s1);
    k_global<<<128, 128, 0, s1>>>();
    cudaEventRecord(eGlob, s1);

    // s2: prep_x (consumed by dense)
    k_prep_x<<<dim3(32, 128), 256, 0, s2>>>(xq, xk);
    cudaEventRecord(ePx, s2);

    // main: prep_of -> sim -> dense -> final
    k_prep_of<<<dim3(32, 128), 256>>>(ofq, ofk);
    cudaStreamWaitEvent(0, eAgn, 0);
    k_simargmax<<<dim3(4, 64), 256, SIM_SMEM>>>();
    cudaStreamWaitEvent(0, ePx, 0);
    k_dense<<<dim3(8, 64, 2), 256, DEN_SMEM>>>(adq, adk);
    cudaStreamWaitEvent(0, eGlob, 0);
    k_final<<<1, 1>>>(epoch, out);
}

// round 13
// speedup vs baseline: 1.2100x; 1.2100x over previous
#include <cuda_runtime.h>
#include <cuda_fp16.h>
#include <stdint.h>

#define TINV 10.0f

__device__ float d_agn[128 * 128];
__device__ float d_ofinv[128 * 1024];
__device__ __half d_ofh[128ull * 1024 * 256];  // [bb][s][d] f16; bb: q 0-63, k 64-127
__device__ float d_xn[2][64 * 1024 * 128];     // normalized x, [b][s][c] f32
__device__ __half d_xh[2][64 * 1024 * 128];    // normalized x, f16 copy
__device__ unsigned long long d_rowbest[64 * 1024];
__device__ unsigned long long d_colbest[64 * 1024];
__device__ double d_gsum, d_dsum;

// ---------------- helpers ----------------
__device__ __forceinline__ uint32_t smem_u32(const void* p) {
    uint32_t a;
    asm("{ .reg .u64 t; cvta.to.shared.u64 t, %1; cvt.u32.u64 %0, t; }" : "=r"(a) : "l"(p));
    return a;
}
__device__ __forceinline__ uint32_t fkey(float f) {
    uint32_t u = __float_as_uint(f);
    return (u & 0x80000000u) ? ~u : (u | 0x80000000u);
}
__device__ __forceinline__ unsigned long long packkey(float v, uint32_t idx) {
    return ((unsigned long long)fkey(v) << 32) | (unsigned long long)(0xFFFFFFFFu - idx);
}
__device__ __forceinline__ unsigned long long shflx64(unsigned long long v, int m) {
    return __shfl_xor_sync(0xFFFFFFFFu, v, m);
}
__device__ __forceinline__ void cp16(uint32_t dst, const void* src) {
    asm volatile("cp.async.cg.shared.global [%0],[%1],16;\n" :: "r"(dst), "l"(src));
}
#define CP_COMMIT() asm volatile("cp.async.commit_group;\n" ::: "memory")
__device__ __forceinline__ void ldsm4(uint32_t& r0, uint32_t& r1, uint32_t& r2,
                                      uint32_t& r3, uint32_t a) {
    asm volatile("ldmatrix.sync.aligned.m8n8.x4.shared.b16 {%0,%1,%2,%3},[%4];\n"
                 : "=r"(r0), "=r"(r1), "=r"(r2), "=r"(r3) : "r"(a));
}
__device__ __forceinline__ void mma16816h(uint32_t* c, const uint32_t* a, const uint32_t* b) {
    asm volatile("mma.sync.aligned.m16n8k16.row.col.f16.f16.f16.f16 "
                 "{%0,%1},{%2,%3,%4,%5},{%6,%7},{%0,%1};\n"
                 : "+r"(c[0]), "+r"(c[1])
                 : "r"(a[0]), "r"(a[1]), "r"(a[2]), "r"(a[3]), "r"(b[0]), "r"(b[1]));
}
__device__ __forceinline__ void mma16816f(float* c, const uint32_t* a, const uint32_t* b) {
    asm volatile("mma.sync.aligned.m16n8k16.row.col.f32.f16.f16.f32 "
                 "{%0,%1,%2,%3},{%4,%5,%6,%7},{%8,%9},{%0,%1,%2,%3};\n"
                 : "+f"(c[0]), "+f"(c[1]), "+f"(c[2]), "+f"(c[3])
                 : "r"(a[0]), "r"(a[1]), "r"(a[2]), "r"(a[3]), "r"(b[0]), "r"(b[1]));
}

// ---------------- agn (+ scratch init folded in) ----------------
__global__ void k_agn(const float* __restrict__ agq, const float* __restrict__ agk) {
    int row = blockIdx.x, c = threadIdx.x;
    int gt = row * 128 + c;
#pragma unroll
    for (int i = 0; i < 4; i++) {
        d_rowbest[gt * 4 + i] = 0ULL;
        d_colbest[gt * 4 + i] = 0ULL;
    }
    if (gt == 0) { d_gsum = 0.0; d_dsum = 0.0; }

    const float* src = (row < 64) ? (agq + row * 128) : (agk + (row - 64) * 128);
    float v = src[c];
    __shared__ float red[128];
    red[c] = v * v; __syncthreads();
    for (int off = 64; off; off >>= 1) { if (c < off) red[c] += red[c + off]; __syncthreads(); }
    d_agn[row * 128 + c] = v / fmaxf(sqrtf(red[0]), 1e-12f);
}
__global__ void k_global() {
    int i = blockIdx.x, j = threadIdx.x;
    __shared__ float ai[128], red[128], s_pos;
    ai[j] = d_agn[i * 128 + j];
    __syncthreads();
    float dot = 0.0f;
#pragma unroll 8
    for (int c = 0; c < 128; c++) dot += ai[c] * d_agn[j * 128 + c];
    float lg = dot * TINV;
    if (j == ((i + 64) & 127)) s_pos = lg;
    float v = (j == i) ? -1e30f : lg;
    red[j] = v; __syncthreads();
    for (int off = 64; off; off >>= 1) { if (j < off) red[j] = fmaxf(red[j], red[j + off]); __syncthreads(); }
    float mx = red[0]; __syncthreads();
    red[j] = expf(v - mx); __syncthreads();
    for (int off = 64; off; off >>= 1) { if (j < off) red[j] += red[j + off]; __syncthreads(); }
    if (j == 0) atomicAdd(&d_gsum, (double)(logf(red[0]) + mx - s_pos));
}

// ---------------- of: transpose -> [s][d] f16 + col inv-norms ----------------
__global__ void __launch_bounds__(256) k_prep_of(const float* __restrict__ ofq,
                                                 const float* __restrict__ ofk) {
    __shared__ float sh[32 * 257];
    int bb = blockIdx.y, s0 = blockIdx.x * 32, tid = threadIdx.x;
    const float* p = (bb < 64 ? ofq : ofk) + (size_t)(bb & 63) * 256 * 1024;
#pragma unroll
    for (int it = 0; it < 8; it++) {
        int idx = it * 256 + tid;
        int dd = idx >> 3, s4 = idx & 7;
        float4 v = *(const float4*)&p[(size_t)dd * 1024 + s0 + s4 * 4];
        sh[(s4 * 4 + 0) * 257 + dd] = v.x;
        sh[(s4 * 4 + 1) * 257 + dd] = v.y;
        sh[(s4 * 4 + 2) * 257 + dd] = v.z;
        sh[(s4 * 4 + 3) * 257 + dd] = v.w;
    }
    __syncthreads();
    int s = tid >> 3, part = tid & 7, d0 = part * 32;
    const float* row = &sh[s * 257 + d0];
    float acc = 0.0f;
    uint32_t pk[16];
#pragma unroll
    for (int ii = 0; ii < 16; ii++) {
        int i = (ii + part * 2) & 15;
        float a = row[2 * i], b2 = row[2 * i + 1];
        acc += a * a + b2 * b2;
        __half2 h = __floats2half2_rn(a, b2);
        pk[i] = *reinterpret_cast<uint32_t*>(&h);
    }
    acc += __shfl_xor_sync(0xFFFFFFFFu, acc, 1);
    acc += __shfl_xor_sync(0xFFFFFFFFu, acc, 2);
    acc += __shfl_xor_sync(0xFFFFFFFFu, acc, 4);
    if (part == 0) d_ofinv[bb * 1024 + s0 + s] = 1.0f / fmaxf(sqrtf(acc), 1e-12f);
    uint4* dst = (uint4*)(d_ofh + ((size_t)bb * 1024 + s0 + s) * 256 + d0);
#pragma unroll
    for (int q = 0; q < 4; q++)
        dst[q] = make_uint4(pk[q * 4], pk[q * 4 + 1], pk[q * 4 + 2], pk[q * 4 + 3]);
}

// ---------------- x: normalize over C + transpose (f32 + f16 outputs) ----------
__global__ void __launch_bounds__(256) k_prep_x(const float* __restrict__ xq,
                                                const float* __restrict__ xk) {
    __shared__ float sh[128 * 33];
    __shared__ float invs[32];
    int bb = blockIdx.y, s0 = blockIdx.x * 32, tid = threadIdx.x;
    const float* src = (bb < 64 ? xq : xk) + (size_t)(bb & 63) * 128 * 1024;
    int side = bb < 64 ? 0 : 1;
    float* dst = d_xn[side] + (size_t)(bb & 63) * 1024 * 128;
    __half* dsth = d_xh[side] + (size_t)(bb & 63) * 1024 * 128;
#pragma unroll
    for (int it = 0; it < 4; it++) {
        int idx = it * 256 + tid;
        int c = idx >> 3, s4 = idx & 7;
        float4 v = *(const float4*)&src[(size_t)c * 1024 + s0 + s4 * 4];
        sh[c * 33 + s4 * 4 + 0] = v.x;
        sh[c * 33 + s4 * 4 + 1] = v.y;
        sh[c * 33 + s4 * 4 + 2] = v.z;
        sh[c * 33 + s4 * 4 + 3] = v.w;
    }
    __syncthreads();
    if (tid < 32) {
        float acc = 0.0f;
#pragma unroll 8
        for (int c = 0; c < 128; c++) { float v = sh[c * 33 + tid]; acc += v * v; }
        invs[tid] = 1.0f / fmaxf(sqrtf(acc), 1e-12f);
    }
    __syncthreads();
#pragma unroll
    for (int it = 0; it < 8; it++) {
        int idx = it * 256 + tid, s = idx >> 6, c2 = (idx & 63) * 2;
        float inv = invs[s];
        float a = sh[c2 * 33 + s] * inv, b2 = sh[(c2 + 1) * 33 + s] * inv;
        float2* d2 = (float2*)&dst[(size_t)(s0 + s) * 128 + c2];
        *d2 = make_float2(a, b2);
        __half2 h = __floats2half2_rn(a, b2);
        *(uint32_t*)&dsth[(size_t)(s0 + s) * 128 + c2] = *reinterpret_cast<uint32_t*>(&h);
    }
}

// ---------------- sim GEMM (f16 mma, f16 acc, 2-stage pipeline) + dual argmax ----
#define SIM_SMEM 98304
__global__ void __launch_bounds__(256, 2) k_simargmax() {
    extern __shared__ __align__(16) char dsm[];
    __shared__ float qf[128], kf[256];
    __shared__ unsigned long long s_row[128], s_col[256];
    int tid = threadIdx.x, lane = tid & 31, wid = tid >> 5;
    int b = blockIdx.z, s0 = blockIdx.y * 128, t0 = blockIdx.x * 256;
    const char* Aq = (const char*)(d_ofh + ((size_t)b * 1024 + s0) * 256);
    const char* Bq = (const char*)(d_ofh + ((size_t)(64 + b) * 1024 + t0) * 256);

    if (tid < 128) { qf[tid] = d_ofinv[b * 1024 + s0 + tid]; s_row[tid] = 0ULL; }
    kf[tid] = d_ofinv[(64 + b) * 1024 + t0 + tid];
    s_col[tid] = 0ULL;

    uint32_t base = smem_u32(dsm);

#define LOAD_CHUNK(c, st) do { \
    uint32_t ab = base + (st) * 49152, bb2 = ab + 16384; \
    _Pragma("unroll") \
    for (int it = 0; it < 4; it++) { \
        int idx = it * 256 + tid, row = idx >> 3, u = idx & 7; \
        cp16(ab + (uint32_t)row * 128 + (uint32_t)((u ^ (row & 7)) << 4), \
             Aq + (size_t)row * 512 + (c) * 128 + u * 16); \
    } \
    _Pragma("unroll") \
    for (int it = 0; it < 8; it++) { \
        int idx = it * 256 + tid, row = idx >> 3, u = idx & 7; \
        cp16(bb2 + (uint32_t)row * 128 + (uint32_t)((u ^ (row & 7)) << 4), \
             Bq + (size_t)row * 512 + (c) * 128 + u * 16); \
    } \
    CP_COMMIT(); } while (0)

    LOAD_CHUNK(0, 0);
    LOAD_CHUNK(1, 1);

    int wm = wid & 1, wn = wid >> 1;
    int row_in = lane & 15, ub = lane >> 4;
    uint32_t acc[4][8][2];
#pragma unroll
    for (int mi = 0; mi < 4; mi++)
#pragma unroll
        for (int ni = 0; ni < 8; ni++) { acc[mi][ni][0] = 0u; acc[mi][ni][1] = 0u; }

#define DO_CHUNK(C, W) do { \
    asm volatile("cp.async.wait_group %0;\n" :: "n"(W) : "memory"); \
    __syncthreads(); \
    uint32_t ab = base + ((C) & 1) * 49152, bb2 = ab + 16384; \
    _Pragma("unroll") \
    for (int ks = 0; ks < 4; ks++) { \
        int u = ks * 2 + ub; \
        uint32_t af[4][4], bfr[8][2]; \
        _Pragma("unroll") \
        for (int mi = 0; mi < 4; mi++) { \
            int r = wm * 64 + mi * 16 + row_in; \
            ldsm4(af[mi][0], af[mi][1], af[mi][2], af[mi][3], \
                  ab + (uint32_t)r * 128 + (uint32_t)((u ^ (r & 7)) << 4)); \
        } \
        _Pragma("unroll") \
        for (int np = 0; np < 4; np++) { \
            int r = wn * 64 + np * 16 + row_in; \
            uint32_t r0, r1, r2, r3; \
            ldsm4(r0, r1, r2, r3, \
                  bb2 + (uint32_t)r * 128 + (uint32_t)((u ^ (r & 7)) << 4)); \
            bfr[np * 2][0] = r0; bfr[np * 2][1] = r2; \
            bfr[np * 2 + 1][0] = r1; bfr[np * 2 + 1][1] = r3; \
        } \
        _Pragma("unroll") \
        for (int mi = 0; mi < 4; mi++) \
            _Pragma("unroll") \
            for (int ni = 0; ni < 8; ni++) \
                mma16816h(acc[mi][ni], af[mi], bfr[ni]); \
    } \
    if ((C) < 2) { __syncthreads(); LOAD_CHUNK((C) + 2, (C) & 1); } } while (0)

    DO_CHUNK(0, 1);
    DO_CHUNK(1, 1);
    DO_CHUNK(2, 1);
    DO_CHUNK(3, 0);
#undef DO_CHUNK
#undef LOAD_CHUNK

    int g = lane >> 2, tg = lane & 3;
#pragma unroll
    for (int mi = 0; mi < 4; mi++)
#pragma unroll
        for (int rh = 0; rh < 2; rh++) {
            unsigned long long best = 0ULL;
#pragma unroll
            for (int ni = 0; ni < 8; ni++) {
                float2 v = __half22float2(*reinterpret_cast<__half2*>(&acc[mi][ni][rh]));
                int tl0 = wn * 64 + ni * 8 + 2 * tg;
                unsigned long long k0 = packkey(v.x * kf[tl0], (uint32_t)(t0 + tl0));
                unsigned long long k1 = packkey(v.y * kf[tl0 + 1], (uint32_t)(t0 + tl0 + 1));
                if (k0 > best) best = k0;
                if (k1 > best) best = k1;
            }
            unsigned long long o;
            o = shflx64(best, 1); best = (o > best) ? o : best;
            o = shflx64(best, 2); best = (o > best) ? o : best;
            if (tg == 0)
                atomicMax(&s_row[wm * 64 + mi * 16 + g + 8 * rh], best);
        }
#pragma unroll
    for (int ni = 0; ni < 8; ni++)
#pragma unroll
        for (int cp = 0; cp < 2; cp++) {
            int tl = wn * 64 + ni * 8 + 2 * tg + cp;
            unsigned long long best = 0ULL;
#pragma unroll
            for (int mi = 0; mi < 4; mi++)
#pragma unroll
                for (int rh = 0; rh < 2; rh++) {
                    __half2 h = *reinterpret_cast<__half2*>(&acc[mi][ni][rh]);
                    float vv = cp ? __high2float(h) : __low2float(h);
                    int sl = wm * 64 + mi * 16 + g + 8 * rh;
                    unsigned long long k2 = packkey(vv * qf[sl], (uint32_t)(s0 + sl));
                    if (k2 > best) best = k2;
                }
            unsigned long long o;
            o = shflx64(best, 4);  best = (o > best) ? o : best;
            o = shflx64(best, 8);  best = (o > best) ? o : best;
            o = shflx64(best, 16); best = (o > best) ? o : best;
            if (g == 0) atomicMax(&s_col[tl], best);
        }
    __syncthreads();
    if (tid < 128) atomicMax(&d_rowbest[(size_t)b * 1024 + s0 + tid], s_row[tid]);
    atomicMax(&d_colbest[(size_t)b * 1024 + t0 + tid], s_col[tid]);
}

// ---------------- dense losses: tensor-core neg GEMM + CE ----------------
#define DEN_SMEM 49152
__global__ void __launch_bounds__(256, 2) k_dense(const float* __restrict__ adq,
                                                  const float* __restrict__ adk) {
    extern __shared__ __align__(16) char dsm[];
    __shared__ float posv[128];
    int b = blockIdx.y, dir = blockIdx.z, s0 = blockIdx.x * 128;
    const __half* xhA = d_xh[dir] + (size_t)b * 1024 * 128;
    const float* xA = d_xn[dir] + (size_t)b * 1024 * 128;
    const float* xB = d_xn[dir ^ 1] + (size_t)b * 1024 * 128;
    const float* ad = dir ? adq : adk;
    const unsigned long long* best = dir ? d_colbest : d_rowbest;

    int tid = threadIdx.x, lane = tid & 31, wid = tid >> 5;
    uint32_t a_base = smem_u32(dsm), b_base = a_base + 32768;
    float* Ls = (float*)dsm;

#pragma unroll
    for (int it = 0; it < 8; it++) {
        int idx = it * 256 + tid, row = idx >> 4, u = idx & 15;
        cp16(a_base + (uint32_t)row * 256 + (uint32_t)(((u & 8) | ((u & 7) ^ (row & 7))) << 4),
             (const char*)xhA + (size_t)(s0 + row) * 256 + u * 16);
    }
    CP_COMMIT();
#pragma unroll
    for (int it = 0; it < 4; it++) {
        int idx = it * 256 + tid, j = idx >> 4, u = idx & 15;
        float4 v0 = *(const float4*)&ad[j * 128 + u * 8];
        float4 v1 = *(const float4*)&ad[j * 128 + u * 8 + 4];
        __half2 h0 = __floats2half2_rn(v0.x, v0.y), h1 = __floats2half2_rn(v0.z, v0.w);
        __half2 h2 = __floats2half2_rn(v1.x, v1.y), h3 = __floats2half2_rn(v1.z, v1.w);
        uint4 pk = make_uint4(*(uint32_t*)&h0, *(uint32_t*)&h1, *(uint32_t*)&h2, *(uint32_t*)&h3);
        *(uint4*)(dsm + 32768 + j * 256 + (((u & 8) | ((u & 7) ^ (j & 7))) << 4)) = pk;
    }
    for (int rr = 0; rr < 16; rr++) {
        int r = wid * 16 + rr, sgl = s0 + r;
        unsigned long long bk = best[b * 1024 + sgl];
        int ind = (int)(0xFFFFFFFFu - (uint32_t)(bk & 0xFFFFFFFFull));
        float sum = 0.0f;
#pragma unroll
        for (int c = lane; c < 128; c += 32)
            sum += xA[(size_t)sgl * 128 + c] * xB[(size_t)ind * 128 + c];
#pragma unroll
        for (int off = 16; off; off >>= 1) sum += __shfl_xor_sync(0xFFFFFFFFu, sum, off);
        if (lane == 0) posv[r] = sum * TINV;
    }
    asm volatile("cp.async.wait_group 0;\n" ::: "memory");
    __syncthreads();

    int wm = wid & 3, wn = wid >> 2;
    int row_in = lane & 15, ub = lane >> 4;
    float acc[2][4][4];
#pragma unroll
    for (int mi = 0; mi < 2; mi++)
#pragma unroll
        for (int ni = 0; ni < 4; ni++)
#pragma unroll
            for (int r = 0; r < 4; r++) acc[mi][ni][r] = 0.0f;
#pragma unroll
    for (int ks = 0; ks < 8; ks++) {
        int u = ks * 2 + ub;
        uint32_t af[2][4], bfr[4][2];
#pragma unroll
        for (int mi = 0; mi < 2; mi++) {
            int r = wm * 32 + mi * 16 + row_in;
            ldsm4(af[mi][0], af[mi][1], af[mi][2], af[mi][3],
                  a_base + (uint32_t)r * 256 + (uint32_t)(((u & 8) | ((u & 7) ^ (r & 7))) << 4));
        }
#pragma unroll
        for (int np = 0; np < 2; np++) {
            int r = wn * 32 + np * 16 + row_in;
            uint32_t r0, r1, r2, r3;
            ldsm4(r0, r1, r2, r3,
                  b_base + (uint32_t)r * 256 + (uint32_t)(((u & 8) | ((u & 7) ^ (r & 7))) << 4));
            bfr[np * 2][0] = r0; bfr[np * 2][1] = r2;
            bfr[np * 2 + 1][0] = r1; bfr[np * 2 + 1][1] = r3;
        }
#pragma unroll
        for (int mi = 0; mi < 2; mi++)
#pragma unroll
            for (int ni = 0; ni < 4; ni++)
                mma16816f(acc[mi][ni], af[mi], bfr[ni]);
    }
    __syncthreads();

    int g = lane >> 2, tg = lane & 3;
#pragma unroll
    for (int mi = 0; mi < 2; mi++)
#pragma unroll
        for (int ni = 0; ni < 4; ni++)
#pragma unroll
            for (int rh = 0; rh < 2; rh++)
#pragma unroll
                for (int cp = 0; cp < 2; cp++) {
                    int r = wm * 32 + mi * 16 + g + 8 * rh;
                    int c = wn * 32 + ni * 8 + 2 * tg + cp;
                    Ls[r * 65 + c] = acc[mi][ni][rh * 2 + cp] * TINV;
                }
    __syncthreads();

    float wsum = 0.0f;
    for (int rr = 0; rr < 16; rr++) {
        int r = wid * 16 + rr;
        float v0 = Ls[r * 65 + lane], v1 = Ls[r * 65 + lane + 32];
        if (lane == b) v0 = -1e30f;
        if (lane + 32 == b) v1 = -1e30f;
        float pos = posv[r];
        float mx = fmaxf(fmaxf(v0, v1), pos);
#pragma unroll
        for (int off = 16; off; off >>= 1) mx = fmaxf(mx, __shfl_xor_sync(0xFFFFFFFFu, mx, off));
        float e = expf(v0 - mx) + expf(v1 - mx);
#pragma unroll
        for (int off = 16; off; off >>= 1) e += __shfl_xor_sync(0xFFFFFFFFu, e, off);
        if (lane == 0) wsum += logf(e + expf(pos - mx)) + mx - pos;
    }
    if (lane == 0) atomicAdd(&d_dsum, (double)wsum);
}

__global__ void k_final(const int* __restrict__ epoch, float* __restrict__ out) {
    float g = (float)(d_gsum / 128.0);
    float d = (float)(d_dsum / 131072.0);
    out[0] = (*epoch > 0) ? (0.5f * g + 0.5f * d) : g;
}

extern "C" void kernel_launch(void* const* d_in, const int* in_sizes, int n_in,
                              void* d_out, int out_size) {
    const float* ofq = (const float*)d_in[0];
    const float* agq = (const float*)d_in[1];
    const float* xq  = (const float*)d_in[2];
    const float* adq = (const float*)d_in[3];
    const float* ofk = (const float*)d_in[4];
    const float* agk = (const float*)d_in[5];
    const float* xk  = (const float*)d_in[6];
    const float* adk = (const float*)d_in[7];
    const int* epoch = (const int*)d_in[8];
    float* out = (float*)d_out;

    static bool init_done = false;
    static cudaStream_t s1, s2;
    static cudaEvent_t eFork, eAgn, eGlob, ePx, eOf;
    if (!init_done) {
        cudaFuncSetAttribute(k_simargmax, cudaFuncAttributeMaxDynamicSharedMemorySize, SIM_SMEM);
        cudaFuncSetAttribute(k_dense, cudaFuncAttributeMaxDynamicSharedMemorySize, DEN_SMEM);
        cudaStreamCreateWithFlags(&s1, cudaStreamNonBlocking);
        cudaStreamCreateWithFlags(&s2, cudaStreamNonBlocking);
        cudaEventCreateWithFlags(&eFork, cudaEventDisableTiming);
        cudaEventCreateWithFlags(&eAgn, cudaEventDisableTiming);
        cudaEventCreateWithFlags(&eGlob, cudaEventDisableTiming);
        cudaEventCreateWithFlags(&ePx, cudaEventDisableTiming);
        cudaEventCreateWithFlags(&eOf, cudaEventDisableTiming);
        init_done = true;
    }

    cudaEventRecord(eFork, 0);
    cudaStreamWaitEvent(s1, eFork, 0);
    cudaStreamWaitEvent(s2, eFork, 0);

    // s1: agn (zeroes scratch) -> global (tiny; negligible contention)
    k_agn<<<128, 128, 0, s1>>>(agq, agk);
    cudaEventRecord(eAgn, s1);
    k_global<<<128, 128, 0, s1>>>();
    cudaEventRecord(eGlob, s1);

    // main: prep_of runs FIRST and uncontended (critical path)
    k_prep_of<<<dim3(32, 128), 256>>>(ofq, ofk);
    cudaEventRecord(eOf, 0);

    // s2: prep_x AFTER prep_of -> overlaps with tensor-bound sim instead
    cudaStreamWaitEvent(s2, eOf, 0);
    k_prep_x<<<dim3(32, 128), 256, 0, s2>>>(xq, xk);
    cudaEventRecord(ePx, s2);

    // main: sim -> dense -> final
    cudaStreamWaitEvent(0, eAgn, 0);
    k_simargmax<<<dim3(4, 8, 64), 256, SIM_SMEM>>>();
    cudaStreamWaitEvent(0, ePx, 0);
    k_dense<<<dim3(8, 64, 2), 256, DEN_SMEM>>>(adq, adk);
    cudaStreamWaitEvent(0, eGlob, 0);
    k_final<<<1, 1>>>(epoch, out);
}

// round 14
// speedup vs baseline: 1.3146x; 1.0865x over previous
#include <cuda_runtime.h>
#include <cuda_fp16.h>
#include <stdint.h>

#define TINV 10.0f

__device__ float d_agn[128 * 128];
__device__ float d_ofinv[128 * 1024];
__device__ __half d_ofh[128ull * 1024 * 256];  // [bb][s][d] f16; bb: q 0-63, k 64-127
__device__ __half d_xh[2][64 * 1024 * 128];    // normalized x, f16, [b][s][c]
__device__ unsigned long long d_rowbest[64 * 1024];
__device__ unsigned long long d_colbest[64 * 1024];
__device__ double d_gsum, d_dsum;

// ---------------- helpers ----------------
__device__ __forceinline__ uint32_t smem_u32(const void* p) {
    uint32_t a;
    asm("{ .reg .u64 t; cvta.to.shared.u64 t, %1; cvt.u32.u64 %0, t; }" : "=r"(a) : "l"(p));
    return a;
}
__device__ __forceinline__ uint32_t fkey(float f) {
    uint32_t u = __float_as_uint(f);
    return (u & 0x80000000u) ? ~u : (u | 0x80000000u);
}
__device__ __forceinline__ unsigned long long packkey(float v, uint32_t idx) {
    return ((unsigned long long)fkey(v) << 32) | (unsigned long long)(0xFFFFFFFFu - idx);
}
__device__ __forceinline__ unsigned long long shflx64(unsigned long long v, int m) {
    return __shfl_xor_sync(0xFFFFFFFFu, v, m);
}
__device__ __forceinline__ void cp16(uint32_t dst, const void* src) {
    asm volatile("cp.async.cg.shared.global [%0],[%1],16;\n" :: "r"(dst), "l"(src));
}
#define CP_COMMIT() asm volatile("cp.async.commit_group;\n" ::: "memory")
__device__ __forceinline__ void ldsm4(uint32_t& r0, uint32_t& r1, uint32_t& r2,
                                      uint32_t& r3, uint32_t a) {
    asm volatile("ldmatrix.sync.aligned.m8n8.x4.shared.b16 {%0,%1,%2,%3},[%4];\n"
                 : "=r"(r0), "=r"(r1), "=r"(r2), "=r"(r3) : "r"(a));
}
__device__ __forceinline__ void mma16816h(uint32_t* c, const uint32_t* a, const uint32_t* b) {
    asm volatile("mma.sync.aligned.m16n8k16.row.col.f16.f16.f16.f16 "
                 "{%0,%1},{%2,%3,%4,%5},{%6,%7},{%0,%1};\n"
                 : "+r"(c[0]), "+r"(c[1])
                 : "r"(a[0]), "r"(a[1]), "r"(a[2]), "r"(a[3]), "r"(b[0]), "r"(b[1]));
}
__device__ __forceinline__ void mma16816f(float* c, const uint32_t* a, const uint32_t* b) {
    asm volatile("mma.sync.aligned.m16n8k16.row.col.f32.f16.f16.f32 "
                 "{%0,%1,%2,%3},{%4,%5,%6,%7},{%8,%9},{%0,%1,%2,%3};\n"
                 : "+f"(c[0]), "+f"(c[1]), "+f"(c[2]), "+f"(c[3])
                 : "r"(a[0]), "r"(a[1]), "r"(a[2]), "r"(a[3]), "r"(b[0]), "r"(b[1]));
}

// ---------------- agn (+ scratch init folded in) ----------------
__global__ void k_agn(const float* __restrict__ agq, const float* __restrict__ agk) {
    int row = blockIdx.x, c = threadIdx.x;
    int gt = row * 128 + c;
#pragma unroll
    for (int i = 0; i < 4; i++) {
        d_rowbest[gt * 4 + i] = 0ULL;
        d_colbest[gt * 4 + i] = 0ULL;
    }
    if (gt == 0) { d_gsum = 0.0; d_dsum = 0.0; }

    const float* src = (row < 64) ? (agq + row * 128) : (agk + (row - 64) * 128);
    float v = src[c];
    __shared__ float red[128];
    red[c] = v * v; __syncthreads();
    for (int off = 64; off; off >>= 1) { if (c < off) red[c] += red[c + off]; __syncthreads(); }
    d_agn[row * 128 + c] = v / fmaxf(sqrtf(red[0]), 1e-12f);
}
__global__ void k_global() {
    int i = blockIdx.x, j = threadIdx.x;
    __shared__ float ai[128], red[128], s_pos;
    ai[j] = d_agn[i * 128 + j];
    __syncthreads();
    float dot = 0.0f;
#pragma unroll 8
    for (int c = 0; c < 128; c++) dot += ai[c] * d_agn[j * 128 + c];
    float lg = dot * TINV;
    if (j == ((i + 64) & 127)) s_pos = lg;
    float v = (j == i) ? -1e30f : lg;
    red[j] = v; __syncthreads();
    for (int off = 64; off; off >>= 1) { if (j < off) red[j] = fmaxf(red[j], red[j + off]); __syncthreads(); }
    float mx = red[0]; __syncthreads();
    red[j] = expf(v - mx); __syncthreads();
    for (int off = 64; off; off >>= 1) { if (j < off) red[j] += red[j + off]; __syncthreads(); }
    if (j == 0) atomicAdd(&d_gsum, (double)(logf(red[0]) + mx - s_pos));
}

// ---------------- of: transpose -> [s][d] f16 + col inv-norms ----------------
__global__ void __launch_bounds__(256) k_prep_of(const float* __restrict__ ofq,
                                                 const float* __restrict__ ofk) {
    __shared__ float sh[32 * 257];
    int bb = blockIdx.y, s0 = blockIdx.x * 32, tid = threadIdx.x;
    const float* p = (bb < 64 ? ofq : ofk) + (size_t)(bb & 63) * 256 * 1024;
#pragma unroll
    for (int it = 0; it < 8; it++) {
        int idx = it * 256 + tid;
        int dd = idx >> 3, s4 = idx & 7;
        float4 v = *(const float4*)&p[(size_t)dd * 1024 + s0 + s4 * 4];
        sh[(s4 * 4 + 0) * 257 + dd] = v.x;
        sh[(s4 * 4 + 1) * 257 + dd] = v.y;
        sh[(s4 * 4 + 2) * 257 + dd] = v.z;
        sh[(s4 * 4 + 3) * 257 + dd] = v.w;
    }
    __syncthreads();
    int s = tid >> 3, part = tid & 7, d0 = part * 32;
    const float* row = &sh[s * 257 + d0];
    float acc = 0.0f;
    uint32_t pk[16];
#pragma unroll
    for (int ii = 0; ii < 16; ii++) {
        int i = (ii + part * 2) & 15;
        float a = row[2 * i], b2 = row[2 * i + 1];
        acc += a * a + b2 * b2;
        __half2 h = __floats2half2_rn(a, b2);
        pk[i] = *reinterpret_cast<uint32_t*>(&h);
    }
    acc += __shfl_xor_sync(0xFFFFFFFFu, acc, 1);
    acc += __shfl_xor_sync(0xFFFFFFFFu, acc, 2);
    acc += __shfl_xor_sync(0xFFFFFFFFu, acc, 4);
    if (part == 0) d_ofinv[bb * 1024 + s0 + s] = 1.0f / fmaxf(sqrtf(acc), 1e-12f);
    uint4* dst = (uint4*)(d_ofh + ((size_t)bb * 1024 + s0 + s) * 256 + d0);
#pragma unroll
    for (int q = 0; q < 4; q++)
        dst[q] = make_uint4(pk[q * 4], pk[q * 4 + 1], pk[q * 4 + 2], pk[q * 4 + 3]);
}

// ---------------- x: normalize over C + transpose (f16 output only) ----------
__global__ void __launch_bounds__(256) k_prep_x(const float* __restrict__ xq,
                                                const float* __restrict__ xk) {
    __shared__ float sh[128 * 33];
    __shared__ float invs[32];
    int bb = blockIdx.y, s0 = blockIdx.x * 32, tid = threadIdx.x;
    const float* src = (bb < 64 ? xq : xk) + (size_t)(bb & 63) * 128 * 1024;
    int side = bb < 64 ? 0 : 1;
    __half* dsth = d_xh[side] + (size_t)(bb & 63) * 1024 * 128;
#pragma unroll
    for (int it = 0; it < 4; it++) {
        int idx = it * 256 + tid;
        int c = idx >> 3, s4 = idx & 7;
        float4 v = *(const float4*)&src[(size_t)c * 1024 + s0 + s4 * 4];
        sh[c * 33 + s4 * 4 + 0] = v.x;
        sh[c * 33 + s4 * 4 + 1] = v.y;
        sh[c * 33 + s4 * 4 + 2] = v.z;
        sh[c * 33 + s4 * 4 + 3] = v.w;
    }
    __syncthreads();
    if (tid < 32) {
        float acc = 0.0f;
#pragma unroll 8
        for (int c = 0; c < 128; c++) { float v = sh[c * 33 + tid]; acc += v * v; }
        invs[tid] = 1.0f / fmaxf(sqrtf(acc), 1e-12f);
    }
    __syncthreads();
#pragma unroll
    for (int it = 0; it < 8; it++) {
        int idx = it * 256 + tid, s = idx >> 6, c2 = (idx & 63) * 2;
        float inv = invs[s];
        float a = sh[c2 * 33 + s] * inv, b2 = sh[(c2 + 1) * 33 + s] * inv;
        __half2 h = __floats2half2_rn(a, b2);
        *(uint32_t*)&dsth[(size_t)(s0 + s) * 128 + c2] = *reinterpret_cast<uint32_t*>(&h);
    }
}

// ---------------- sim GEMM (f16 mma, f16 acc, 2-stage pipeline) + dual argmax ----
#define SIM_SMEM 98304
__global__ void __launch_bounds__(256, 2) k_simargmax() {
    extern __shared__ __align__(16) char dsm[];
    __shared__ float qf[128], kf[256];
    __shared__ unsigned long long s_row[128], s_col[256];
    int tid = threadIdx.x, lane = tid & 31, wid = tid >> 5;
    int b = blockIdx.z, s0 = blockIdx.y * 128, t0 = blockIdx.x * 256;
    const char* Aq = (const char*)(d_ofh + ((size_t)b * 1024 + s0) * 256);
    const char* Bq = (const char*)(d_ofh + ((size_t)(64 + b) * 1024 + t0) * 256);

    if (tid < 128) { qf[tid] = d_ofinv[b * 1024 + s0 + tid]; s_row[tid] = 0ULL; }
    kf[tid] = d_ofinv[(64 + b) * 1024 + t0 + tid];
    s_col[tid] = 0ULL;

    uint32_t base = smem_u32(dsm);

#define LOAD_CHUNK(c, st) do { \
    uint32_t ab = base + (st) * 49152, bb2 = ab + 16384; \
    _Pragma("unroll") \
    for (int it = 0; it < 4; it++) { \
        int idx = it * 256 + tid, row = idx >> 3, u = idx & 7; \
        cp16(ab + (uint32_t)row * 128 + (uint32_t)((u ^ (row & 7)) << 4), \
             Aq + (size_t)row * 512 + (c) * 128 + u * 16); \
    } \
    _Pragma("unroll") \
    for (int it = 0; it < 8; it++) { \
        int idx = it * 256 + tid, row = idx >> 3, u = idx & 7; \
        cp16(bb2 + (uint32_t)row * 128 + (uint32_t)((u ^ (row & 7)) << 4), \
             Bq + (size_t)row * 512 + (c) * 128 + u * 16); \
    } \
    CP_COMMIT(); } while (0)

    LOAD_CHUNK(0, 0);
    LOAD_CHUNK(1, 1);

    int wm = wid & 1, wn = wid >> 1;
    int row_in = lane & 15, ub = lane >> 4;
    uint32_t acc[4][8][2];
#pragma unroll
    for (int mi = 0; mi < 4; mi++)
#pragma unroll
        for (int ni = 0; ni < 8; ni++) { acc[mi][ni][0] = 0u; acc[mi][ni][1] = 0u; }

#define DO_CHUNK(C, W) do { \
    asm volatile("cp.async.wait_group %0;\n" :: "n"(W) : "memory"); \
    __syncthreads(); \
    uint32_t ab = base + ((C) & 1) * 49152, bb2 = ab + 16384; \
    _Pragma("unroll") \
    for (int ks = 0; ks < 4; ks++) { \
        int u = ks * 2 + ub; \
        uint32_t af[4][4], bfr[8][2]; \
        _Pragma("unroll") \
        for (int mi = 0; mi < 4; mi++) { \
            int r = wm * 64 + mi * 16 + row_in; \
            ldsm4(af[mi][0], af[mi][1], af[mi][2], af[mi][3], \
                  ab + (uint32_t)r * 128 + (uint32_t)((u ^ (r & 7)) << 4)); \
        } \
        _Pragma("unroll") \
        for (int np = 0; np < 4; np++) { \
            int r = wn * 64 + np * 16 + row_in; \
            uint32_t r0, r1, r2, r3; \
            ldsm4(r0, r1, r2, r3, \
                  bb2 + (uint32_t)r * 128 + (uint32_t)((u ^ (r & 7)) << 4)); \
            bfr[np * 2][0] = r0; bfr[np * 2][1] = r2; \
            bfr[np * 2 + 1][0] = r1; bfr[np * 2 + 1][1] = r3; \
        } \
        _Pragma("unroll") \
        for (int mi = 0; mi < 4; mi++) \
            _Pragma("unroll") \
            for (int ni = 0; ni < 8; ni++) \
                mma16816h(acc[mi][ni], af[mi], bfr[ni]); \
    } \
    if ((C) < 2) { __syncthreads(); LOAD_CHUNK((C) + 2, (C) & 1); } } while (0)

    DO_CHUNK(0, 1);
    DO_CHUNK(1, 1);
    DO_CHUNK(2, 1);
    DO_CHUNK(3, 0);
#undef DO_CHUNK
#undef LOAD_CHUNK

    int g = lane >> 2, tg = lane & 3;
#pragma unroll
    for (int mi = 0; mi < 4; mi++)
#pragma unroll
        for (int rh = 0; rh < 2; rh++) {
            unsigned long long best = 0ULL;
#pragma unroll
            for (int ni = 0; ni < 8; ni++) {
                float2 v = __half22float2(*reinterpret_cast<__half2*>(&acc[mi][ni][rh]));
                int tl0 = wn * 64 + ni * 8 + 2 * tg;
                unsigned long long k0 = packkey(v.x * kf[tl0], (uint32_t)(t0 + tl0));
                unsigned long long k1 = packkey(v.y * kf[tl0 + 1], (uint32_t)(t0 + tl0 + 1));
                if (k0 > best) best = k0;
                if (k1 > best) best = k1;
            }
            unsigned long long o;
            o = shflx64(best, 1); best = (o > best) ? o : best;
            o = shflx64(best, 2); best = (o > best) ? o : best;
            if (tg == 0)
                atomicMax(&s_row[wm * 64 + mi * 16 + g + 8 * rh], best);
        }
#pragma unroll
    for (int ni = 0; ni < 8; ni++)
#pragma unroll
        for (int cp = 0; cp < 2; cp++) {
            int tl = wn * 64 + ni * 8 + 2 * tg + cp;
            unsigned long long best = 0ULL;
#pragma unroll
            for (int mi = 0; mi < 4; mi++)
#pragma unroll
                for (int rh = 0; rh < 2; rh++) {
                    __half2 h = *reinterpret_cast<__half2*>(&acc[mi][ni][rh]);
                    float vv = cp ? __high2float(h) : __low2float(h);
                    int sl = wm * 64 + mi * 16 + g + 8 * rh;
                    unsigned long long k2 = packkey(vv * qf[sl], (uint32_t)(s0 + sl));
                    if (k2 > best) best = k2;
                }
            unsigned long long o;
            o = shflx64(best, 4);  best = (o > best) ? o : best;
            o = shflx64(best, 8);  best = (o > best) ? o : best;
            o = shflx64(best, 16); best = (o > best) ? o : best;
            if (g == 0) atomicMax(&s_col[tl], best);
        }
    __syncthreads();
    if (tid < 128) atomicMax(&d_rowbest[(size_t)b * 1024 + s0 + tid], s_row[tid]);
    atomicMax(&d_colbest[(size_t)b * 1024 + t0 + tid], s_col[tid]);
}

// ---------------- dense losses: tensor-core neg GEMM + CE ----------------
#define DEN_SMEM 49152
__global__ void __launch_bounds__(256, 2) k_dense(const float* __restrict__ adq,
                                                  const float* __restrict__ adk) {
    extern __shared__ __align__(16) char dsm[];
    __shared__ float posv[128];
    int b = blockIdx.y, dir = blockIdx.z, s0 = blockIdx.x * 128;
    const __half* xhA = d_xh[dir] + (size_t)b * 1024 * 128;
    const __half* xhB = d_xh[dir ^ 1] + (size_t)b * 1024 * 128;
    const float* ad = dir ? adq : adk;
    const unsigned long long* best = dir ? d_colbest : d_rowbest;

    int tid = threadIdx.x, lane = tid & 31, wid = tid >> 5;
    uint32_t a_base = smem_u32(dsm), b_base = a_base + 32768;
    float* Ls = (float*)dsm;

#pragma unroll
    for (int it = 0; it < 8; it++) {
        int idx = it * 256 + tid, row = idx >> 4, u = idx & 15;
        cp16(a_base + (uint32_t)row * 256 + (uint32_t)(((u & 8) | ((u & 7) ^ (row & 7))) << 4),
             (const char*)xhA + (size_t)(s0 + row) * 256 + u * 16);
    }
    CP_COMMIT();
#pragma unroll
    for (int it = 0; it < 4; it++) {
        int idx = it * 256 + tid, j = idx >> 4, u = idx & 15;
        float4 v0 = *(const float4*)&ad[j * 128 + u * 8];
        float4 v1 = *(const float4*)&ad[j * 128 + u * 8 + 4];
        __half2 h0 = __floats2half2_rn(v0.x, v0.y), h1 = __floats2half2_rn(v0.z, v0.w);
        __half2 h2 = __floats2half2_rn(v1.x, v1.y), h3 = __floats2half2_rn(v1.z, v1.w);
        uint4 pk = make_uint4(*(uint32_t*)&h0, *(uint32_t*)&h1, *(uint32_t*)&h2, *(uint32_t*)&h3);
        *(uint4*)(dsm + 32768 + j * 256 + (((u & 8) | ((u & 7) ^ (j & 7))) << 4)) = pk;
    }
    // pos gather from f16 normalized x (f32 accumulate)
    for (int rr = 0; rr < 16; rr++) {
        int r = wid * 16 + rr, sgl = s0 + r;
        unsigned long long bk = best[b * 1024 + sgl];
        int ind = (int)(0xFFFFFFFFu - (uint32_t)(bk & 0xFFFFFFFFull));
        const __half2* a2 = (const __half2*)(xhA + (size_t)sgl * 128);
        const __half2* b2v = (const __half2*)(xhB + (size_t)ind * 128);
        float sum = 0.0f;
#pragma unroll
        for (int c = lane; c < 64; c += 32) {
            float2 fa = __half22float2(a2[c]);
            float2 fb = __half22float2(b2v[c]);
            sum += fa.x * fb.x + fa.y * fb.y;
        }
#pragma unroll
        for (int off = 16; off; off >>= 1) sum += __shfl_xor_sync(0xFFFFFFFFu, sum, off);
        if (lane == 0) posv[r] = sum * TINV;
    }
    asm volatile("cp.async.wait_group 0;\n" ::: "memory");
    __syncthreads();

    int wm = wid & 3, wn = wid >> 2;
    int row_in = lane & 15, ub = lane >> 4;
    float acc[2][4][4];
#pragma unroll
    for (int mi = 0; mi < 2; mi++)
#pragma unroll
        for (int ni = 0; ni < 4; ni++)
#pragma unroll
            for (int r = 0; r < 4; r++) acc[mi][ni][r] = 0.0f;
#pragma unroll
    for (int ks = 0; ks < 8; ks++) {
        int u = ks * 2 + ub;
        uint32_t af[2][4], bfr[4][2];
#pragma unroll
        for (int mi = 0; mi < 2; mi++) {
            int r = wm * 32 + mi * 16 + row_in;
            ldsm4(af[mi][0], af[mi][1], af[mi][2], af[mi][3],
                  a_base + (uint32_t)r * 256 + (uint32_t)(((u & 8) | ((u & 7) ^ (r & 7))) << 4));
        }
#pragma unroll
        for (int np = 0; np < 2; np++) {
            int r = wn * 32 + np * 16 + row_in;
            uint32_t r0, r1, r2, r3;
            ldsm4(r0, r1, r2, r3,
                  b_base + (uint32_t)r * 256 + (uint32_t)(((u & 8) | ((u & 7) ^ (r & 7))) << 4));
            bfr[np * 2][0] = r0; bfr[np * 2][1] = r2;
            bfr[np * 2 + 1][0] = r1; bfr[np * 2 + 1][1] = r3;
        }
#pragma unroll
        for (int mi = 0; mi < 2; mi++)
#pragma unroll
            for (int ni = 0; ni < 4; ni++)
                mma16816f(acc[mi][ni], af[mi], bfr[ni]);
    }
    __syncthreads();

    int g = lane >> 2, tg = lane & 3;
#pragma unroll
    for (int mi = 0; mi < 2; mi++)
#pragma unroll
        for (int ni = 0; ni < 4; ni++)
#pragma unroll
            for (int rh = 0; rh < 2; rh++)
#pragma unroll
                for (int cp = 0; cp < 2; cp++) {
                    int r = wm * 32 + mi * 16 + g + 8 * rh;
                    int c = wn * 32 + ni * 8 + 2 * tg + cp;
                    Ls[r * 65 + c] = acc[mi][ni][rh * 2 + cp] * TINV;
                }
    __syncthreads();

    float wsum = 0.0f;
    for (int rr = 0; rr < 16; rr++) {
        int r = wid * 16 + rr;
        float v0 = Ls[r * 65 + lane], v1 = Ls[r * 65 + lane + 32];
        if (lane == b) v0 = -1e30f;
        if (lane + 32 == b) v1 = -1e30f;
        float pos = posv[r];
        float mx = fmaxf(fmaxf(v0, v1), pos);
#pragma unroll
        for (int off = 16; off; off >>= 1) mx = fmaxf(mx, __shfl_xor_sync(0xFFFFFFFFu, mx, off));
        float e = expf(v0 - mx) + expf(v1 - mx);
#pragma unroll
        for (int off = 16; off; off >>= 1) e += __shfl_xor_sync(0xFFFFFFFFu, e, off);
        if (lane == 0) wsum += logf(e + expf(pos - mx)) + mx - pos;
    }
    if (lane == 0) atomicAdd(&d_dsum, (double)wsum);
}

__global__ void k_final(const int* __restrict__ epoch, float* __restrict__ out) {
    float g = (float)(d_gsum / 128.0);
    float d = (float)(d_dsum / 131072.0);
    out[0] = (*epoch > 0) ? (0.5f * g + 0.5f * d) : g;
}

extern "C" void kernel_launch(void* const* d_in, const int* in_sizes, int n_in,
                              void* d_out, int out_size) {
    const float* ofq = (const float*)d_in[0];
    const float* agq = (const float*)d_in[1];
    const float* xq  = (const float*)d_in[2];
    const float* adq = (const float*)d_in[3];
    const float* ofk = (const float*)d_in[4];
    const float* agk = (const float*)d_in[5];
    const float* xk  = (const float*)d_in[6];
    const float* adk = (const float*)d_in[7];
    const int* epoch = (const int*)d_in[8];
    float* out = (float*)d_out;

    static bool init_done = false;
    static cudaStream_t s1, s2;
    static cudaEvent_t eFork, eAgn, eGlob, ePx;
    if (!init_done) {
        cudaFuncSetAttribute(k_simargmax, cudaFuncAttributeMaxDynamicSharedMemorySize, SIM_SMEM);
        cudaFuncSetAttribute(k_dense, cudaFuncAttributeMaxDynamicSharedMemorySize, DEN_SMEM);
        cudaStreamCreateWithFlags(&s1, cudaStreamNonBlocking);
        cudaStreamCreateWithFlags(&s2, cudaStreamNonBlocking);
        cudaEventCreateWithFlags(&eFork, cudaEventDisableTiming);
        cudaEventCreateWithFlags(&eAgn, cudaEventDisableTiming);
        cudaEventCreateWithFlags(&eGlob, cudaEventDisableTiming);
        cudaEventCreateWithFlags(&ePx, cudaEventDisableTiming);
        init_done = true;
    }

    cudaEventRecord(eFork, 0);
    cudaStreamWaitEvent(s1, eFork, 0);
    cudaStreamWaitEvent(s2, eFork, 0);

    // s1: agn (zeroes scratch) -> global
    k_agn<<<128, 128, 0, s1>>>(agq, agk);
    cudaEventRecord(eAgn, s1);
    k_global<<<128, 128, 0, s1>>>();
    cudaEventRecord(eGlob, s1);

    // s2: prep_x concurrent with prep_of (R9 placement — proven best)
    k_prep_x<<<dim3(32, 128), 256, 0, s2>>>(xq, xk);
    cudaEventRecord(ePx, s2);

    // main: prep_of -> sim -> dense -> final
    k_prep_of<<<dim3(32, 128), 256>>>(ofq, ofk);
    cudaStreamWaitEvent(0, eAgn, 0);
    k_simargmax<<<dim3(4, 8, 64), 256, SIM_SMEM>>>();
    cudaStreamWaitEvent(0, ePx, 0);
    k_dense<<<dim3(8, 64, 2), 256, DEN_SMEM>>>(adq, adk);
    cudaStreamWaitEvent(0, eGlob, 0);
    k_final<<<1, 1>>>(epoch, out);
}

// round 15
// speedup vs baseline: 1.3575x; 1.0326x over previous
#include <cuda_runtime.h>
#include <cuda_fp16.h>
#include <stdint.h>

#define TINV 10.0f

__device__ float d_agn[128 * 128];
__device__ float d_ofinv[128 * 1024];
__device__ __half d_ofh[128ull * 1024 * 256];  // [bb][s][d] f16; bb: q 0-63, k 64-127
__device__ __half d_xh[2][64 * 1024 * 128];    // normalized x, f16, [b][s][c]
__device__ unsigned long long d_rowbest[64 * 1024];
__device__ unsigned long long d_colbest[64 * 1024];
__device__ double d_gsum, d_dsum;

// ---------------- helpers ----------------
__device__ __forceinline__ uint32_t smem_u32(const void* p) {
    uint32_t a;
    asm("{ .reg .u64 t; cvta.to.shared.u64 t, %1; cvt.u32.u64 %0, t; }" : "=r"(a) : "l"(p));
    return a;
}
__device__ __forceinline__ uint32_t fkey(float f) {
    uint32_t u = __float_as_uint(f);
    return (u & 0x80000000u) ? ~u : (u | 0x80000000u);
}
__device__ __forceinline__ unsigned long long packkey(float v, uint32_t idx) {
    return ((unsigned long long)fkey(v) << 32) | (unsigned long long)(0xFFFFFFFFu - idx);
}
__device__ __forceinline__ unsigned long long shflx64(unsigned long long v, int m) {
    return __shfl_xor_sync(0xFFFFFFFFu, v, m);
}
__device__ __forceinline__ void cp16(uint32_t dst, const void* src) {
    asm volatile("cp.async.cg.shared.global [%0],[%1],16;\n" :: "r"(dst), "l"(src));
}
#define CP_COMMIT() asm volatile("cp.async.commit_group;\n" ::: "memory")
__device__ __forceinline__ void ldsm4(uint32_t& r0, uint32_t& r1, uint32_t& r2,
                                      uint32_t& r3, uint32_t a) {
    asm volatile("ldmatrix.sync.aligned.m8n8.x4.shared.b16 {%0,%1,%2,%3},[%4];\n"
                 : "=r"(r0), "=r"(r1), "=r"(r2), "=r"(r3) : "r"(a));
}
__device__ __forceinline__ void mma16816h(uint32_t* c, const uint32_t* a, const uint32_t* b) {
    asm volatile("mma.sync.aligned.m16n8k16.row.col.f16.f16.f16.f16 "
                 "{%0,%1},{%2,%3,%4,%5},{%6,%7},{%0,%1};\n"
                 : "+r"(c[0]), "+r"(c[1])
                 : "r"(a[0]), "r"(a[1]), "r"(a[2]), "r"(a[3]), "r"(b[0]), "r"(b[1]));
}
__device__ __forceinline__ void mma16816f(float* c, const uint32_t* a, const uint32_t* b) {
    asm volatile("mma.sync.aligned.m16n8k16.row.col.f32.f16.f16.f32 "
                 "{%0,%1,%2,%3},{%4,%5,%6,%7},{%8,%9},{%0,%1,%2,%3};\n"
                 : "+f"(c[0]), "+f"(c[1]), "+f"(c[2]), "+f"(c[3])
                 : "r"(a[0]), "r"(a[1]), "r"(a[2]), "r"(a[3]), "r"(b[0]), "r"(b[1]));
}

// ---------------- agn (+ scratch init folded in) ----------------
__global__ void k_agn(const float* __restrict__ agq, const float* __restrict__ agk) {
    int row = blockIdx.x, c = threadIdx.x;
    int gt = row * 128 + c;
#pragma unroll
    for (int i = 0; i < 4; i++) {
        d_rowbest[gt * 4 + i] = 0ULL;
        d_colbest[gt * 4 + i] = 0ULL;
    }
    if (gt == 0) { d_gsum = 0.0; d_dsum = 0.0; }

    const float* src = (row < 64) ? (agq + row * 128) : (agk + (row - 64) * 128);
    float v = src[c];
    __shared__ float red[128];
    red[c] = v * v; __syncthreads();
    for (int off = 64; off; off >>= 1) { if (c < off) red[c] += red[c + off]; __syncthreads(); }
    d_agn[row * 128 + c] = v / fmaxf(sqrtf(red[0]), 1e-12f);
}
__global__ void k_global() {
    int i = blockIdx.x, j = threadIdx.x;
    __shared__ float ai[128], red[128], s_pos;
    ai[j] = d_agn[i * 128 + j];
    __syncthreads();
    float dot = 0.0f;
#pragma unroll 8
    for (int c = 0; c < 128; c++) dot += ai[c] * d_agn[j * 128 + c];
    float lg = dot * TINV;
    if (j == ((i + 64) & 127)) s_pos = lg;
    float v = (j == i) ? -1e30f : lg;
    red[j] = v; __syncthreads();
    for (int off = 64; off; off >>= 1) { if (j < off) red[j] = fmaxf(red[j], red[j + off]); __syncthreads(); }
    float mx = red[0]; __syncthreads();
    red[j] = expf(v - mx); __syncthreads();
    for (int off = 64; off; off >>= 1) { if (j < off) red[j] += red[j + off]; __syncthreads(); }
    if (j == 0) atomicAdd(&d_gsum, (double)(logf(red[0]) + mx - s_pos));
}

// ---------------- of: transpose -> [s][d] f16 + col inv-norms ----------------
__global__ void __launch_bounds__(256) k_prep_of(const float* __restrict__ ofq,
                                                 const float* __restrict__ ofk) {
    __shared__ float sh[32 * 257];
    int bb = blockIdx.y, s0 = blockIdx.x * 32, tid = threadIdx.x;
    const float* p = (bb < 64 ? ofq : ofk) + (size_t)(bb & 63) * 256 * 1024;
#pragma unroll
    for (int it = 0; it < 8; it++) {
        int idx = it * 256 + tid;
        int dd = idx >> 3, s4 = idx & 7;
        float4 v = *(const float4*)&p[(size_t)dd * 1024 + s0 + s4 * 4];
        sh[(s4 * 4 + 0) * 257 + dd] = v.x;
        sh[(s4 * 4 + 1) * 257 + dd] = v.y;
        sh[(s4 * 4 + 2) * 257 + dd] = v.z;
        sh[(s4 * 4 + 3) * 257 + dd] = v.w;
    }
    __syncthreads();
    int s = tid >> 3, part = tid & 7, d0 = part * 32;
    const float* row = &sh[s * 257 + d0];
    float acc = 0.0f;
    uint32_t pk[16];
#pragma unroll
    for (int ii = 0; ii < 16; ii++) {
        int i = (ii + part * 2) & 15;
        float a = row[2 * i], b2 = row[2 * i + 1];
        acc += a * a + b2 * b2;
        __half2 h = __floats2half2_rn(a, b2);
        pk[i] = *reinterpret_cast<uint32_t*>(&h);
    }
    acc += __shfl_xor_sync(0xFFFFFFFFu, acc, 1);
    acc += __shfl_xor_sync(0xFFFFFFFFu, acc, 2);
    acc += __shfl_xor_sync(0xFFFFFFFFu, acc, 4);
    if (part == 0) d_ofinv[bb * 1024 + s0 + s] = 1.0f / fmaxf(sqrtf(acc), 1e-12f);
    uint4* dst = (uint4*)(d_ofh + ((size_t)bb * 1024 + s0 + s) * 256 + d0);
#pragma unroll
    for (int q = 0; q < 4; q++)
        dst[q] = make_uint4(pk[q * 4], pk[q * 4 + 1], pk[q * 4 + 2], pk[q * 4 + 3]);
}

// ---------------- x: normalize over C + transpose (f16 output only) ----------
__global__ void __launch_bounds__(256) k_prep_x(const float* __restrict__ xq,
                                                const float* __restrict__ xk) {
    __shared__ float sh[128 * 33];
    __shared__ float invs[32];
    int bb = blockIdx.y, s0 = blockIdx.x * 32, tid = threadIdx.x;
    const float* src = (bb < 64 ? xq : xk) + (size_t)(bb & 63) * 128 * 1024;
    int side = bb < 64 ? 0 : 1;
    __half* dsth = d_xh[side] + (size_t)(bb & 63) * 1024 * 128;
#pragma unroll
    for (int it = 0; it < 4; it++) {
        int idx = it * 256 + tid;
        int c = idx >> 3, s4 = idx & 7;
        float4 v = *(const float4*)&src[(size_t)c * 1024 + s0 + s4 * 4];
        sh[c * 33 + s4 * 4 + 0] = v.x;
        sh[c * 33 + s4 * 4 + 1] = v.y;
        sh[c * 33 + s4 * 4 + 2] = v.z;
        sh[c * 33 + s4 * 4 + 3] = v.w;
    }
    __syncthreads();
    if (tid < 32) {
        float acc = 0.0f;
#pragma unroll 8
        for (int c = 0; c < 128; c++) { float v = sh[c * 33 + tid]; acc += v * v; }
        invs[tid] = 1.0f / fmaxf(sqrtf(acc), 1e-12f);
    }
    __syncthreads();
#pragma unroll
    for (int it = 0; it < 8; it++) {
        int idx = it * 256 + tid, s = idx >> 6, c2 = (idx & 63) * 2;
        float inv = invs[s];
        float a = sh[c2 * 33 + s] * inv, b2 = sh[(c2 + 1) * 33 + s] * inv;
        __half2 h = __floats2half2_rn(a, b2);
        *(uint32_t*)&dsth[(size_t)(s0 + s) * 128 + c2] = *reinterpret_cast<uint32_t*>(&h);
    }
}

// ---------------- sim GEMM: 128x128 tile, 3 CTAs/SM, f16 acc + dual argmax ----
#define SIM_SMEM 65536
__global__ void __launch_bounds__(256, 3) k_simargmax() {
    extern __shared__ __align__(16) char dsm[];
    __shared__ float qf[128], kf[128];
    __shared__ unsigned long long s_row[128], s_col[128];
    int tid = threadIdx.x, lane = tid & 31, wid = tid >> 5;
    int b = blockIdx.z, s0 = blockIdx.y * 128, t0 = blockIdx.x * 128;
    const char* Aq = (const char*)(d_ofh + ((size_t)b * 1024 + s0) * 256);
    const char* Bq = (const char*)(d_ofh + ((size_t)(64 + b) * 1024 + t0) * 256);

    if (tid < 128) { qf[tid] = d_ofinv[b * 1024 + s0 + tid]; s_row[tid] = 0ULL; }
    else { kf[tid - 128] = d_ofinv[(64 + b) * 1024 + t0 + tid - 128]; s_col[tid - 128] = 0ULL; }

    uint32_t base = smem_u32(dsm);

#define LOAD_CHUNK(c, st) do { \
    uint32_t ab = base + (st) * 32768, bb2 = ab + 16384; \
    _Pragma("unroll") \
    for (int it = 0; it < 4; it++) { \
        int idx = it * 256 + tid, row = idx >> 3, u = idx & 7; \
        cp16(ab + (uint32_t)row * 128 + (uint32_t)((u ^ (row & 7)) << 4), \
             Aq + (size_t)row * 512 + (c) * 128 + u * 16); \
    } \
    _Pragma("unroll") \
    for (int it = 0; it < 4; it++) { \
        int idx = it * 256 + tid, row = idx >> 3, u = idx & 7; \
        cp16(bb2 + (uint32_t)row * 128 + (uint32_t)((u ^ (row & 7)) << 4), \
             Bq + (size_t)row * 512 + (c) * 128 + u * 16); \
    } \
    CP_COMMIT(); } while (0)

    LOAD_CHUNK(0, 0);
    LOAD_CHUNK(1, 1);

    int wm = wid & 3, wn = wid >> 2;      // warp tile: rows wm*32, cols wn*64
    int row_in = lane & 15, ub = lane >> 4;
    uint32_t acc[2][8][2];
#pragma unroll
    for (int mi = 0; mi < 2; mi++)
#pragma unroll
        for (int ni = 0; ni < 8; ni++) { acc[mi][ni][0] = 0u; acc[mi][ni][1] = 0u; }

#define DO_CHUNK(C, W) do { \
    asm volatile("cp.async.wait_group %0;\n" :: "n"(W) : "memory"); \
    __syncthreads(); \
    uint32_t ab = base + ((C) & 1) * 32768, bb2 = ab + 16384; \
    _Pragma("unroll") \
    for (int ks = 0; ks < 4; ks++) { \
        int u = ks * 2 + ub; \
        uint32_t af[2][4], bfr[8][2]; \
        _Pragma("unroll") \
        for (int mi = 0; mi < 2; mi++) { \
            int r = wm * 32 + mi * 16 + row_in; \
            ldsm4(af[mi][0], af[mi][1], af[mi][2], af[mi][3], \
                  ab + (uint32_t)r * 128 + (uint32_t)((u ^ (r & 7)) << 4)); \
        } \
        _Pragma("unroll") \
        for (int np = 0; np < 4; np++) { \
            int r = wn * 64 + np * 16 + row_in; \
            uint32_t r0, r1, r2, r3; \
            ldsm4(r0, r1, r2, r3, \
                  bb2 + (uint32_t)r * 128 + (uint32_t)((u ^ (r & 7)) << 4)); \
            bfr[np * 2][0] = r0; bfr[np * 2][1] = r2; \
            bfr[np * 2 + 1][0] = r1; bfr[np * 2 + 1][1] = r3; \
        } \
        _Pragma("unroll") \
        for (int mi = 0; mi < 2; mi++) \
            _Pragma("unroll") \
            for (int ni = 0; ni < 8; ni++) \
                mma16816h(acc[mi][ni], af[mi], bfr[ni]); \
    } \
    if ((C) < 2) { __syncthreads(); LOAD_CHUNK((C) + 2, (C) & 1); } } while (0)

    DO_CHUNK(0, 1);
    DO_CHUNK(1, 1);
    DO_CHUNK(2, 1);
    DO_CHUNK(3, 0);
#undef DO_CHUNK
#undef LOAD_CHUNK

    int g = lane >> 2, tg = lane & 3;
    // row argmax (over t-cols): weight kf
#pragma unroll
    for (int mi = 0; mi < 2; mi++)
#pragma unroll
        for (int rh = 0; rh < 2; rh++) {
            unsigned long long best = 0ULL;
#pragma unroll
            for (int ni = 0; ni < 8; ni++) {
                float2 v = __half22float2(*reinterpret_cast<__half2*>(&acc[mi][ni][rh]));
                int tl0 = wn * 64 + ni * 8 + 2 * tg;
                unsigned long long k0 = packkey(v.x * kf[tl0], (uint32_t)(t0 + tl0));
                unsigned long long k1 = packkey(v.y * kf[tl0 + 1], (uint32_t)(t0 + tl0 + 1));
                if (k0 > best) best = k0;
                if (k1 > best) best = k1;
            }
            unsigned long long o;
            o = shflx64(best, 1); best = (o > best) ? o : best;
            o = shflx64(best, 2); best = (o > best) ? o : best;
            if (tg == 0)
                atomicMax(&s_row[wm * 32 + mi * 16 + g + 8 * rh], best);
        }
    // col argmax (over s-rows): weight qf
#pragma unroll
    for (int ni = 0; ni < 8; ni++)
#pragma unroll
        for (int cp = 0; cp < 2; cp++) {
            int tl = wn * 64 + ni * 8 + 2 * tg + cp;
            unsigned long long best = 0ULL;
#pragma unroll
            for (int mi = 0; mi < 2; mi++)
#pragma unroll
                for (int rh = 0; rh < 2; rh++) {
                    __half2 h = *reinterpret_cast<__half2*>(&acc[mi][ni][rh]);
                    float vv = cp ? __high2float(h) : __low2float(h);
                    int sl = wm * 32 + mi * 16 + g + 8 * rh;
                    unsigned long long k2 = packkey(vv * qf[sl], (uint32_t)(s0 + sl));
                    if (k2 > best) best = k2;
                }
            unsigned long long o;
            o = shflx64(best, 4);  best = (o > best) ? o : best;
            o = shflx64(best, 8);  best = (o > best) ? o : best;
            o = shflx64(best, 16); best = (o > best) ? o : best;
            if (g == 0) atomicMax(&s_col[tl], best);
        }
    __syncthreads();
    if (tid < 128) atomicMax(&d_rowbest[(size_t)b * 1024 + s0 + tid], s_row[tid]);
    else atomicMax(&d_colbest[(size_t)b * 1024 + t0 + tid - 128], s_col[tid - 128]);
}

// ---------------- dense losses: tensor-core neg GEMM + CE ----------------
#define DEN_SMEM 49152
__global__ void __launch_bounds__(256, 2) k_dense(const float* __restrict__ adq,
                                                  const float* __restrict__ adk) {
    extern __shared__ __align__(16) char dsm[];
    __shared__ float posv[128];
    int b = blockIdx.y, dir = blockIdx.z, s0 = blockIdx.x * 128;
    const __half* xhA = d_xh[dir] + (size_t)b * 1024 * 128;
    const __half* xhB = d_xh[dir ^ 1] + (size_t)b * 1024 * 128;
    const float* ad = dir ? adq : adk;
    const unsigned long long* best = dir ? d_colbest : d_rowbest;

    int tid = threadIdx.x, lane = tid & 31, wid = tid >> 5;
    uint32_t a_base = smem_u32(dsm), b_base = a_base + 32768;
    float* Ls = (float*)dsm;

#pragma unroll
    for (int it = 0; it < 8; it++) {
        int idx = it * 256 + tid, row = idx >> 4, u = idx & 15;
        cp16(a_base + (uint32_t)row * 256 + (uint32_t)(((u & 8) | ((u & 7) ^ (row & 7))) << 4),
             (const char*)xhA + (size_t)(s0 + row) * 256 + u * 16);
    }
    CP_COMMIT();
#pragma unroll
    for (int it = 0; it < 4; it++) {
        int idx = it * 256 + tid, j = idx >> 4, u = idx & 15;
        float4 v0 = *(const float4*)&ad[j * 128 + u * 8];
        float4 v1 = *(const float4*)&ad[j * 128 + u * 8 + 4];
        __half2 h0 = __floats2half2_rn(v0.x, v0.y), h1 = __floats2half2_rn(v0.z, v0.w);
        __half2 h2 = __floats2half2_rn(v1.x, v1.y), h3 = __floats2half2_rn(v1.z, v1.w);
        uint4 pk = make_uint4(*(uint32_t*)&h0, *(uint32_t*)&h1, *(uint32_t*)&h2, *(uint32_t*)&h3);
        *(uint4*)(dsm + 32768 + j * 256 + (((u & 8) | ((u & 7) ^ (j & 7))) << 4)) = pk;
    }
    for (int rr = 0; rr < 16; rr++) {
        int r = wid * 16 + rr, sgl = s0 + r;
        unsigned long long bk = best[b * 1024 + sgl];
        int ind = (int)(0xFFFFFFFFu - (uint32_t)(bk & 0xFFFFFFFFull));
        const __half2* a2 = (const __half2*)(xhA + (size_t)sgl * 128);
        const __half2* b2v = (const __half2*)(xhB + (size_t)ind * 128);
        float sum = 0.0f;
#pragma unroll
        for (int c = lane; c < 64; c += 32) {
            float2 fa = __half22float2(a2[c]);
            float2 fb = __half22float2(b2v[c]);
            sum += fa.x * fb.x + fa.y * fb.y;
        }
#pragma unroll
        for (int off = 16; off; off >>= 1) sum += __shfl_xor_sync(0xFFFFFFFFu, sum, off);
        if (lane == 0) posv[r] = sum * TINV;
    }
    asm volatile("cp.async.wait_group 0;\n" ::: "memory");
    __syncthreads();

    int wm = wid & 3, wn = wid >> 2;
    int row_in = lane & 15, ub = lane >> 4;
    float acc[2][4][4];
#pragma unroll
    for (int mi = 0; mi < 2; mi++)
#pragma unroll
        for (int ni = 0; ni < 4; ni++)
#pragma unroll
            for (int r = 0; r < 4; r++) acc[mi][ni][r] = 0.0f;
#pragma unroll
    for (int ks = 0; ks < 8; ks++) {
        int u = ks * 2 + ub;
        uint32_t af[2][4], bfr[4][2];
#pragma unroll
        for (int mi = 0; mi < 2; mi++) {
            int r = wm * 32 + mi * 16 + row_in;
            ldsm4(af[mi][0], af[mi][1], af[mi][2], af[mi][3],
                  a_base + (uint32_t)r * 256 + (uint32_t)(((u & 8) | ((u & 7) ^ (r & 7))) << 4));
        }
#pragma unroll
        for (int np = 0; np < 2; np++) {
            int r = wn * 32 + np * 16 + row_in;
            uint32_t r0, r1, r2, r3;
            ldsm4(r0, r1, r2, r3,
                  b_base + (uint32_t)r * 256 + (uint32_t)(((u & 8) | ((u & 7) ^ (r & 7))) << 4));
            bfr[np * 2][0] = r0; bfr[np * 2][1] = r2;
            bfr[np * 2 + 1][0] = r1; bfr[np * 2 + 1][1] = r3;
        }
#pragma unroll
        for (int mi = 0; mi < 2; mi++)
#pragma unroll
            for (int ni = 0; ni < 4; ni++)
                mma16816f(acc[mi][ni], af[mi], bfr[ni]);
    }
    __syncthreads();

    int g = lane >> 2, tg = lane & 3;
#pragma unroll
    for (int mi = 0; mi < 2; mi++)
#pragma unroll
        for (int ni = 0; ni < 4; ni++)
#pragma unroll
            for (int rh = 0; rh < 2; rh++)
#pragma unroll
                for (int cp = 0; cp < 2; cp++) {
                    int r = wm * 32 + mi * 16 + g + 8 * rh;
                    int c = wn * 32 + ni * 8 + 2 * tg + cp;
                    Ls[r * 65 + c] = acc[mi][ni][rh * 2 + cp] * TINV;
                }
    __syncthreads();

    float wsum = 0.0f;
    for (int rr = 0; rr < 16; rr++) {
        int r = wid * 16 + rr;
        float v0 = Ls[r * 65 + lane], v1 = Ls[r * 65 + lane + 32];
        if (lane == b) v0 = -1e30f;
        if (lane + 32 == b) v1 = -1e30f;
        float pos = posv[r];
        float mx = fmaxf(fmaxf(v0, v1), pos);
#pragma unroll
        for (int off = 16; off; off >>= 1) mx = fmaxf(mx, __shfl_xor_sync(0xFFFFFFFFu, mx, off));
        float e = expf(v0 - mx) + expf(v1 - mx);
#pragma unroll
        for (int off = 16; off; off >>= 1) e += __shfl_xor_sync(0xFFFFFFFFu, e, off);
        if (lane == 0) wsum += logf(e + expf(pos - mx)) + mx - pos;
    }
    if (lane == 0) atomicAdd(&d_dsum, (double)wsum);
}

__global__ void k_final(const int* __restrict__ epoch, float* __restrict__ out) {
    float g = (float)(d_gsum / 128.0);
    float d = (float)(d_dsum / 131072.0);
    out[0] = (*epoch > 0) ? (0.5f * g + 0.5f * d) : g;
}

extern "C" void kernel_launch(void* const* d_in, const int* in_sizes, int n_in,
                              void* d_out, int out_size) {
    const float* ofq = (const float*)d_in[0];
    const float* agq = (const float*)d_in[1];
    const float* xq  = (const float*)d_in[2];
    const float* adq = (const float*)d_in[3];
    const float* ofk = (const float*)d_in[4];
    const float* agk = (const float*)d_in[5];
    const float* xk  = (const float*)d_in[6];
    const float* adk = (const float*)d_in[7];
    const int* epoch = (const int*)d_in[8];
    float* out = (float*)d_out;

    static bool init_done = false;
    static cudaStream_t s1, s2;
    static cudaEvent_t eFork, eAgn, eGlob, ePx;
    if (!init_done) {
        cudaFuncSetAttribute(k_simargmax, cudaFuncAttributeMaxDynamicSharedMemorySize, SIM_SMEM);
        cudaFuncSetAttribute(k_dense, cudaFuncAttributeMaxDynamicSharedMemorySize, DEN_SMEM);
        cudaStreamCreateWithFlags(&s1, cudaStreamNonBlocking);
        cudaStreamCreateWithFlags(&s2, cudaStreamNonBlocking);
        cudaEventCreateWithFlags(&eFork, cudaEventDisableTiming);
        cudaEventCreateWithFlags(&eAgn, cudaEventDisableTiming);
        cudaEventCreateWithFlags(&eGlob, cudaEventDisableTiming);
        cudaEventCreateWithFlags(&ePx, cudaEventDisableTiming);
        init_done = true;
    }

    cudaEventRecord(eFork, 0);
    cudaStreamWaitEvent(s1, eFork, 0);
    cudaStreamWaitEvent(s2, eFork, 0);

    // s1: agn (zeroes scratch) -> global
    k_agn<<<128, 128, 0, s1>>>(agq, agk);
    cudaEventRecord(eAgn, s1);
    k_global<<<128, 128, 0, s1>>>();
    cudaEventRecord(eGlob, s1);

    // s2: prep_x concurrent with prep_of
    k_prep_x<<<dim3(32, 128), 256, 0, s2>>>(xq, xk);
    cudaEventRecord(ePx, s2);

    // main: prep_of -> sim -> dense -> final
    k_prep_of<<<dim3(32, 128), 256>>>(ofq, ofk);
    cudaStreamWaitEvent(0, eAgn, 0);
    k_simargmax<<<dim3(8, 8, 64), 256, SIM_SMEM>>>();
    cudaStreamWaitEvent(0, ePx, 0);
    k_dense<<<dim3(8, 64, 2), 256, DEN_SMEM>>>(adq, adk);
    cudaStreamWaitEvent(0, eGlob, 0);
    k_final<<<1, 1>>>(epoch, out);
}